// round 1
// baseline (speedup 1.0000x reference)
#include <cuda_runtime.h>
#include <cstdint>
#include <math.h>

// Problem dims: B=2, S=2048, D=2048, H=16, DH=128, DFF=8192
#define BSD 8388608   // B*S*D
#define BSF 33554432  // B*S*DFF

// ---------------- scratch (static device globals; no runtime allocation) ---
__device__ float g_xn[BSD];
__device__ float g_q[BSD];
__device__ float g_k[BSD];
__device__ float g_v[BSD];
__device__ float g_attn[BSD];
__device__ float g_x1[BSD];
__device__ float g_h[BSF];

// ---------------- helpers --------------------------------------------------
__device__ __forceinline__ float to_tf32(float x) {
    float r; asm("cvt.rna.tf32.f32 %0, %1;" : "=f"(r) : "f"(x)); return r;
}

__device__ __forceinline__ void mma8(float* d, const uint32_t* a, const uint32_t* b) {
    asm volatile(
        "mma.sync.aligned.m16n8k8.row.col.f32.tf32.tf32.f32 "
        "{%0,%1,%2,%3}, {%4,%5,%6,%7}, {%8,%9}, {%0,%1,%2,%3};\n"
        : "+f"(d[0]), "+f"(d[1]), "+f"(d[2]), "+f"(d[3])
        : "r"(a[0]), "r"(a[1]), "r"(a[2]), "r"(a[3]), "r"(b[0]), "r"(b[1]));
}

__device__ __forceinline__ float gelu_f(float v) {
    return 0.5f * v * (1.0f + erff(v * 0.70710678118654752f));
}

// All 256 threads get the block-wide sum.
__device__ __forceinline__ float block_sum256(float v) {
    __shared__ float red[8];
    #pragma unroll
    for (int o = 16; o; o >>= 1) v += __shfl_xor_sync(0xffffffffu, v, o);
    const int w = threadIdx.x >> 5, l = threadIdx.x & 31;
    __syncthreads();                 // protect red reuse across calls
    if (l == 0) red[w] = v;
    __syncthreads();
    float t = red[l & 7];
    t += __shfl_xor_sync(0xffffffffu, t, 1);
    t += __shfl_xor_sync(0xffffffffu, t, 2);
    t += __shfl_xor_sync(0xffffffffu, t, 4);
    return t;
}

// ---------------- LayerNorm: one block per row (D=2048, 256 thr x 8 elems) -
__global__ __launch_bounds__(256) void ln_kernel(
    const float* __restrict__ x, const float* __restrict__ gw,
    const float* __restrict__ bw, float* __restrict__ y)
{
    const size_t base = (size_t)blockIdx.x * 2048;
    const int tid = threadIdx.x;
    const float4 v0 = *(const float4*)&x[base + tid * 4];
    const float4 v1 = *(const float4*)&x[base + 1024 + tid * 4];

    float s = v0.x + v0.y + v0.z + v0.w + v1.x + v1.y + v1.z + v1.w;
    const float mean = block_sum256(s) * (1.0f / 2048.0f);

    const float d0 = v0.x - mean, d1 = v0.y - mean, d2 = v0.z - mean, d3 = v0.w - mean;
    const float d4 = v1.x - mean, d5 = v1.y - mean, d6 = v1.z - mean, d7 = v1.w - mean;
    float q = d0*d0 + d1*d1 + d2*d2 + d3*d3 + d4*d4 + d5*d5 + d6*d6 + d7*d7;
    const float var = block_sum256(q) * (1.0f / 2048.0f);
    const float rs = rsqrtf(var + 1e-5f);

    const float4 g0 = *(const float4*)&gw[tid * 4];
    const float4 g1 = *(const float4*)&gw[1024 + tid * 4];
    const float4 b0 = *(const float4*)&bw[tid * 4];
    const float4 b1 = *(const float4*)&bw[1024 + tid * 4];

    float4 o0 = make_float4(d0*rs*g0.x + b0.x, d1*rs*g0.y + b0.y,
                            d2*rs*g0.z + b0.z, d3*rs*g0.w + b0.w);
    float4 o1 = make_float4(d4*rs*g1.x + b1.x, d5*rs*g1.y + b1.y,
                            d6*rs*g1.z + b1.z, d7*rs*g1.w + b1.w);
    *(float4*)&y[base + tid * 4] = o0;
    *(float4*)&y[base + 1024 + tid * 4] = o1;
}

// ---------------- TF32 tensor-core GEMM ------------------------------------
// C[M,N] = A[M,K] @ W[K,N] (+bias) (+res) (+gelu). CTA tile 128x128, K-tile 32.
// 8 warps as 4(m) x 2(n); warp tile 32x64 via m16n8k8 tf32 mma.
template<int ACT, int HASRES>
__global__ __launch_bounds__(256) void gemm_tf32(
    const float* __restrict__ A, const float* __restrict__ W,
    const float* __restrict__ bias, const float* __restrict__ res,
    float* __restrict__ C, int M, int N, int K)
{
    __shared__ float As[128][36];   // [m][k], pad 36 -> conflict-free frag loads
    __shared__ float Bs[32][132];   // [k][n], pad 132

    const int tid  = threadIdx.x;
    const int warp = tid >> 5, lane = tid & 31;
    const int wm = warp >> 1, wn = warp & 1;
    const int g = lane >> 2, t4 = lane & 3;
    const int bm = blockIdx.y << 7, bn = blockIdx.x << 7;

    const float* Ab = A + (size_t)bm * K;
    const float* Wb = W + bn;

    float4 pa[4], pb[4];
    #pragma unroll
    for (int i = 0; i < 4; i++) {
        const int f4 = tid + (i << 8);
        pa[i] = *(const float4*)&Ab[(size_t)(f4 >> 3) * K + ((f4 & 7) << 2)];
        pb[i] = *(const float4*)&Wb[(size_t)(f4 >> 5) * N + ((f4 & 31) << 2)];
    }

    float acc[2][8][4];
    #pragma unroll
    for (int a = 0; a < 2; a++)
        #pragma unroll
        for (int b2 = 0; b2 < 8; b2++)
            #pragma unroll
            for (int c = 0; c < 4; c++) acc[a][b2][c] = 0.f;

    const int KT = K >> 5;
    for (int kt = 0; kt < KT; kt++) {
        // stage (with tf32 rounding) into smem
        #pragma unroll
        for (int i = 0; i < 4; i++) {
            const int f4 = tid + (i << 8);
            *(float4*)&As[f4 >> 3][(f4 & 7) << 2] =
                make_float4(to_tf32(pa[i].x), to_tf32(pa[i].y), to_tf32(pa[i].z), to_tf32(pa[i].w));
            *(float4*)&Bs[f4 >> 5][(f4 & 31) << 2] =
                make_float4(to_tf32(pb[i].x), to_tf32(pb[i].y), to_tf32(pb[i].z), to_tf32(pb[i].w));
        }
        __syncthreads();
        if (kt + 1 < KT) {   // prefetch next tile into registers during compute
            const int k0 = (kt + 1) << 5;
            #pragma unroll
            for (int i = 0; i < 4; i++) {
                const int f4 = tid + (i << 8);
                pa[i] = *(const float4*)&Ab[(size_t)(f4 >> 3) * K + k0 + ((f4 & 7) << 2)];
                pb[i] = *(const float4*)&Wb[(size_t)(k0 + (f4 >> 5)) * N + ((f4 & 31) << 2)];
            }
        }
        #pragma unroll
        for (int ks = 0; ks < 4; ks++) {
            const int kb = ks << 3;
            uint32_t af[2][4], bf[8][2];
            #pragma unroll
            for (int mi = 0; mi < 2; mi++) {
                const int mr = (wm << 5) + (mi << 4);
                af[mi][0] = __float_as_uint(As[mr + g    ][kb + t4    ]);
                af[mi][1] = __float_as_uint(As[mr + g + 8][kb + t4    ]);
                af[mi][2] = __float_as_uint(As[mr + g    ][kb + t4 + 4]);
                af[mi][3] = __float_as_uint(As[mr + g + 8][kb + t4 + 4]);
            }
            #pragma unroll
            for (int ni = 0; ni < 8; ni++) {
                const int nc = (wn << 6) + (ni << 3) + g;
                bf[ni][0] = __float_as_uint(Bs[kb + t4    ][nc]);
                bf[ni][1] = __float_as_uint(Bs[kb + t4 + 4][nc]);
            }
            #pragma unroll
            for (int mi = 0; mi < 2; mi++)
                #pragma unroll
                for (int ni = 0; ni < 8; ni++)
                    mma8(acc[mi][ni], af[mi], bf[ni]);
        }
        __syncthreads();
    }

    // epilogue: c0,c1 at (row,2t4),(row,2t4+1); c2,c3 at row+8
    #pragma unroll
    for (int mi = 0; mi < 2; mi++) {
        const int row0 = bm + (wm << 5) + (mi << 4) + g;
        #pragma unroll
        for (int ni = 0; ni < 8; ni++) {
            const int col = bn + (wn << 6) + (ni << 3) + (t4 << 1);
            const float b0 = bias[col], b1 = bias[col + 1];
            float v00 = acc[mi][ni][0] + b0, v01 = acc[mi][ni][1] + b1;
            float v10 = acc[mi][ni][2] + b0, v11 = acc[mi][ni][3] + b1;
            const size_t i0 = (size_t)row0 * N + col;
            const size_t i1 = i0 + (size_t)8 * N;
            if (HASRES) {
                v00 += res[i0]; v01 += res[i0 + 1];
                v10 += res[i1]; v11 += res[i1 + 1];
            }
            if (ACT == 1) {
                v00 = gelu_f(v00); v01 = gelu_f(v01);
                v10 = gelu_f(v10); v11 = gelu_f(v11);
            }
            *(float2*)&C[i0] = make_float2(v00, v01);
            *(float2*)&C[i1] = make_float2(v10, v11);
        }
    }
}

// ---------------- causal flash attention (fp32, online softmax) ------------
// grid: (S/64, B*H). 64 q-rows per CTA, stream 64-wide k-tiles.
__global__ __launch_bounds__(256) void flash_kernel(
    const float* __restrict__ Q, const float* __restrict__ K,
    const float* __restrict__ V, float* __restrict__ O)
{
    extern __shared__ float sm[];
    float* QsT  = sm;           // [128][64]  (transposed: [dh][row])
    float* KsT  = sm + 8192;    // [128][64]
    float* Vs   = sm + 16384;   // [64][128]
    float* Ss   = sm + 24576;   // [64][64]
    float* mrow = sm + 28672;   // [64]
    float* lrow = sm + 28736;   // [64]
    float* arow = sm + 28800;   // [64]

    const int tid = threadIdx.x;
    const int warp = tid >> 5, lane = tid & 31;
    const int b = blockIdx.y >> 4, h = blockIdx.y & 15;
    const int q0 = blockIdx.x << 6;
    const size_t base = ((size_t)b * 2048) * 2048 + (size_t)h * 128;
    const float* Qg = Q + base;
    const float* Kg = K + base;
    const float* Vg = V + base;
    float*       Og = O + base;

    // load Q tile, transposed (conflict-free smem stores)
    {
        const int i = tid & 63, c = tid >> 6;
        #pragma unroll
        for (int l = 0; l < 8; l++) {
            const int k4 = (c << 3) + l;
            const float4 qv = *(const float4*)&Qg[(size_t)(q0 + i) * 2048 + (k4 << 2)];
            QsT[((k4 << 2) + 0) * 64 + i] = qv.x;
            QsT[((k4 << 2) + 1) * 64 + i] = qv.y;
            QsT[((k4 << 2) + 2) * 64 + i] = qv.z;
            QsT[((k4 << 2) + 3) * 64 + i] = qv.w;
        }
    }
    if (tid < 64) { mrow[tid] = -1e30f; lrow[tid] = 0.f; }

    float o[8][4];
    #pragma unroll
    for (int u = 0; u < 8; u++) { o[u][0] = 0; o[u][1] = 0; o[u][2] = 0; o[u][3] = 0; }

    const int ntile = (q0 >> 6) + 1;      // causal: k-tiles 0..q-tile
    for (int kt = 0; kt < ntile; kt++) {
        const int k0 = kt << 6;
        __syncthreads();   // covers Q-load/init and prev-iter PV reads
        // load K tile transposed
        {
            const int i = tid & 63, c = tid >> 6;
            #pragma unroll
            for (int l = 0; l < 8; l++) {
                const int k4 = (c << 3) + l;
                const float4 kv = *(const float4*)&Kg[(size_t)(k0 + i) * 2048 + (k4 << 2)];
                KsT[((k4 << 2) + 0) * 64 + i] = kv.x;
                KsT[((k4 << 2) + 1) * 64 + i] = kv.y;
                KsT[((k4 << 2) + 2) * 64 + i] = kv.z;
                KsT[((k4 << 2) + 3) * 64 + i] = kv.w;
            }
        }
        // load V tile row-major (coalesced both sides)
        #pragma unroll
        for (int rr = 0; rr < 8; rr++) {
            const int f4 = tid + (rr << 8);
            const int j = f4 >> 5, c4 = f4 & 31;
            *(float4*)&Vs[j * 128 + (c4 << 2)] =
                *(const float4*)&Vg[(size_t)(k0 + j) * 2048 + (c4 << 2)];
        }
        __syncthreads();

        // S = (Q K^T) * scale, causal mask; thread grid 16x16, 4x4 each
        {
            const int tr = tid >> 4, tc = tid & 15;
            float s[4][4];
            #pragma unroll
            for (int u = 0; u < 4; u++)
                #pragma unroll
                for (int v2 = 0; v2 < 4; v2++) s[u][v2] = 0.f;
            for (int kk = 0; kk < 128; kk++) {
                const float4 qv = *(const float4*)&QsT[kk * 64 + (tr << 2)];
                const float4 kv = *(const float4*)&KsT[kk * 64 + (tc << 2)];
                const float qa[4] = {qv.x, qv.y, qv.z, qv.w};
                const float ka[4] = {kv.x, kv.y, kv.z, kv.w};
                #pragma unroll
                for (int u = 0; u < 4; u++)
                    #pragma unroll
                    for (int v2 = 0; v2 < 4; v2++) s[u][v2] += qa[u] * ka[v2];
            }
            #pragma unroll
            for (int u = 0; u < 4; u++) {
                const int qi = (tr << 2) + u;
                #pragma unroll
                for (int v2 = 0; v2 < 4; v2++) {
                    const int kj = (tc << 2) + v2;
                    float val = s[u][v2] * 0.08838834764831845f;  // 1/sqrt(128)
                    if (k0 + kj > q0 + qi) val = -1e30f;
                    Ss[qi * 64 + kj] = val;
                }
            }
        }
        __syncthreads();

        // online softmax update: 4 threads per row
        {
            const int rid = tid >> 2, c0 = tid & 3;
            float mx = -1e30f;
            #pragma unroll
            for (int jc = c0; jc < 64; jc += 4) mx = fmaxf(mx, Ss[rid * 64 + jc]);
            mx = fmaxf(mx, __shfl_xor_sync(0xffffffffu, mx, 1));
            mx = fmaxf(mx, __shfl_xor_sync(0xffffffffu, mx, 2));
            const float mold = mrow[rid];
            const float mnew = fmaxf(mold, mx);
            float sum = 0.f;
            #pragma unroll
            for (int jc = c0; jc < 64; jc += 4) {
                const float p = __expf(Ss[rid * 64 + jc] - mnew);
                Ss[rid * 64 + jc] = p;
                sum += p;
            }
            sum += __shfl_xor_sync(0xffffffffu, sum, 1);
            sum += __shfl_xor_sync(0xffffffffu, sum, 2);
            if (c0 == 0) {
                arow[rid] = __expf(mold - mnew);
                lrow[rid] = lrow[rid] * arow[rid] + sum;
                mrow[rid] = mnew;
            }
        }
        __syncthreads();

        // O += P @ V : warp w owns rows w*8..w*8+7, lane owns 4 cols
        {
            #pragma unroll
            for (int u = 0; u < 8; u++) {
                const float al = arow[(warp << 3) + u];
                o[u][0] *= al; o[u][1] *= al; o[u][2] *= al; o[u][3] *= al;
            }
            for (int j = 0; j < 64; j++) {
                const float4 vv = *(const float4*)&Vs[j * 128 + (lane << 2)];
                #pragma unroll
                for (int u = 0; u < 8; u++) {
                    const float p = Ss[((warp << 3) + u) * 64 + j];   // broadcast
                    o[u][0] += p * vv.x; o[u][1] += p * vv.y;
                    o[u][2] += p * vv.z; o[u][3] += p * vv.w;
                }
            }
        }
    }

    // normalize + store
    #pragma unroll
    for (int u = 0; u < 8; u++) {
        const int r = (warp << 3) + u;
        const float inv = 1.0f / lrow[r];
        const float4 ov = make_float4(o[u][0] * inv, o[u][1] * inv,
                                      o[u][2] * inv, o[u][3] * inv);
        *(float4*)&Og[(size_t)(q0 + r) * 2048 + (lane << 2)] = ov;
    }
}

// ---------------- host orchestration ---------------------------------------
extern "C" void kernel_launch(void* const* d_in, const int* in_sizes, int n_in,
                              void* d_out, int out_size)
{
    const float* x     = (const float*)d_in[0];
    // d_in[1] = attn_mask (causal tril) — structure exploited directly
    const float* ln1_g = (const float*)d_in[2];
    const float* ln1_b = (const float*)d_in[3];
    const float* wq    = (const float*)d_in[4];
    const float* bq    = (const float*)d_in[5];
    const float* wk    = (const float*)d_in[6];
    const float* bk    = (const float*)d_in[7];
    const float* wv    = (const float*)d_in[8];
    const float* bv    = (const float*)d_in[9];
    const float* wo    = (const float*)d_in[10];
    const float* bo    = (const float*)d_in[11];
    const float* ln2_g = (const float*)d_in[12];
    const float* ln2_b = (const float*)d_in[13];
    const float* w_in  = (const float*)d_in[14];
    const float* b_in  = (const float*)d_in[15];
    const float* w_out = (const float*)d_in[16];
    const float* b_out = (const float*)d_in[17];
    float* out = (float*)d_out;

    float *xn, *q, *k, *v, *attn, *x1, *h;
    cudaGetSymbolAddress((void**)&xn,   g_xn);
    cudaGetSymbolAddress((void**)&q,    g_q);
    cudaGetSymbolAddress((void**)&k,    g_k);
    cudaGetSymbolAddress((void**)&v,    g_v);
    cudaGetSymbolAddress((void**)&attn, g_attn);
    cudaGetSymbolAddress((void**)&x1,   g_x1);
    cudaGetSymbolAddress((void**)&h,    g_h);

    cudaFuncSetAttribute(flash_kernel,
                         cudaFuncAttributeMaxDynamicSharedMemorySize, 115456);

    const dim3 gP(16, 32);   // N=2048 GEMMs: grid (N/128, M/128), M=4096

    ln_kernel<<<4096, 256>>>(x, ln1_g, ln1_b, xn);
    gemm_tf32<0,0><<<gP, 256>>>(xn, wq, bq, nullptr, q, 4096, 2048, 2048);
    gemm_tf32<0,0><<<gP, 256>>>(xn, wk, bk, nullptr, k, 4096, 2048, 2048);
    gemm_tf32<0,0><<<gP, 256>>>(xn, wv, bv, nullptr, v, 4096, 2048, 2048);
    flash_kernel<<<dim3(32, 32), 256, 115456>>>(q, k, v, attn);
    gemm_tf32<0,1><<<gP, 256>>>(attn, wo, bo, x, x1, 4096, 2048, 2048);
    ln_kernel<<<4096, 256>>>(x1, ln2_g, ln2_b, xn);
    gemm_tf32<1,0><<<dim3(64, 32), 256>>>(xn, w_in, b_in, nullptr, h, 4096, 8192, 2048);
    gemm_tf32<0,1><<<gP, 256>>>(h, w_out, b_out, x1, out, 4096, 2048, 8192);
}

// round 3
// speedup vs baseline: 1.1620x; 1.1620x over previous
#include <cuda_runtime.h>
#include <cstdint>
#include <math.h>

// Problem dims: B=2, S=2048, D=2048, H=16, DH=128, DFF=8192
#define BSD 8388608   // B*S*D
#define BSF 33554432  // B*S*DFF

// ---------------- scratch (static device globals; no runtime allocation) ---
__device__ float g_xn[BSD];
__device__ float g_q[BSD];
__device__ float g_k[BSD];
__device__ float g_v[BSD];
__device__ float g_attn[BSD];
__device__ float g_x1[BSD];
__device__ float g_h[BSF];
// tf32-rounded weight copies (same [K,N] layout as inputs)
__device__ float g_wqr[4194304];
__device__ float g_wkr[4194304];
__device__ float g_wvr[4194304];
__device__ float g_wor[4194304];
__device__ float g_winr[16777216];
__device__ float g_woutr[16777216];

// ---------------- helpers --------------------------------------------------
__device__ __forceinline__ float to_tf32(float x) {
    float r; asm("cvt.rna.tf32.f32 %0, %1;" : "=f"(r) : "f"(x)); return r;
}
__device__ __forceinline__ uint32_t smem_u32(const void* p) {
    uint32_t a;
    asm("{ .reg .u64 t; cvta.to.shared.u64 t, %1; cvt.u32.u64 %0, t; }"
        : "=r"(a) : "l"(p));
    return a;
}
__device__ __forceinline__ void cp16(uint32_t s, const void* g) {
    asm volatile("cp.async.cg.shared.global [%0], [%1], 16;" :: "r"(s), "l"(g));
}
__device__ __forceinline__ void mma8(float* d, const uint32_t* a, const uint32_t* b) {
    asm volatile(
        "mma.sync.aligned.m16n8k8.row.col.f32.tf32.tf32.f32 "
        "{%0,%1,%2,%3}, {%4,%5,%6,%7}, {%8,%9}, {%0,%1,%2,%3};\n"
        : "+f"(d[0]), "+f"(d[1]), "+f"(d[2]), "+f"(d[3])
        : "r"(a[0]), "r"(a[1]), "r"(a[2]), "r"(a[3]), "r"(b[0]), "r"(b[1]));
}
__device__ __forceinline__ float gelu_f(float v) {
    return 0.5f * v * (1.0f + erff(v * 0.70710678118654752f));
}

// ---------------- weight tf32 rounding (elementwise, float4) ---------------
__global__ __launch_bounds__(256) void round_kernel(
    const float* __restrict__ w, float* __restrict__ o, int n4)
{
    const int i = blockIdx.x * 256 + threadIdx.x;
    if (i < n4) {
        const float4 v = *(const float4*)&w[(size_t)i * 4];
        *(float4*)&o[(size_t)i * 4] =
            make_float4(to_tf32(v.x), to_tf32(v.y), to_tf32(v.z), to_tf32(v.w));
    }
}

// ---------------- block reduce ---------------------------------------------
__device__ __forceinline__ float block_sum256(float v) {
    __shared__ float red[8];
    #pragma unroll
    for (int o = 16; o; o >>= 1) v += __shfl_xor_sync(0xffffffffu, v, o);
    const int w = threadIdx.x >> 5, l = threadIdx.x & 31;
    __syncthreads();
    if (l == 0) red[w] = v;
    __syncthreads();
    float t = red[l & 7];
    t += __shfl_xor_sync(0xffffffffu, t, 1);
    t += __shfl_xor_sync(0xffffffffu, t, 2);
    t += __shfl_xor_sync(0xffffffffu, t, 4);
    return t;
}

// ---------------- LayerNorm (tf32-rounded output) --------------------------
__global__ __launch_bounds__(256) void ln_kernel(
    const float* __restrict__ x, const float* __restrict__ gw,
    const float* __restrict__ bw, float* __restrict__ y)
{
    const size_t base = (size_t)blockIdx.x * 2048;
    const int tid = threadIdx.x;
    const float4 v0 = *(const float4*)&x[base + tid * 4];
    const float4 v1 = *(const float4*)&x[base + 1024 + tid * 4];

    float s = v0.x + v0.y + v0.z + v0.w + v1.x + v1.y + v1.z + v1.w;
    const float mean = block_sum256(s) * (1.0f / 2048.0f);

    const float d0 = v0.x - mean, d1 = v0.y - mean, d2 = v0.z - mean, d3 = v0.w - mean;
    const float d4 = v1.x - mean, d5 = v1.y - mean, d6 = v1.z - mean, d7 = v1.w - mean;
    float q = d0*d0 + d1*d1 + d2*d2 + d3*d3 + d4*d4 + d5*d5 + d6*d6 + d7*d7;
    const float var = block_sum256(q) * (1.0f / 2048.0f);
    const float rs = rsqrtf(var + 1e-5f);

    const float4 g0 = *(const float4*)&gw[tid * 4];
    const float4 g1 = *(const float4*)&gw[1024 + tid * 4];
    const float4 b0 = *(const float4*)&bw[tid * 4];
    const float4 b1 = *(const float4*)&bw[1024 + tid * 4];

    float4 o0 = make_float4(to_tf32(d0*rs*g0.x + b0.x), to_tf32(d1*rs*g0.y + b0.y),
                            to_tf32(d2*rs*g0.z + b0.z), to_tf32(d3*rs*g0.w + b0.w));
    float4 o1 = make_float4(to_tf32(d4*rs*g1.x + b1.x), to_tf32(d5*rs*g1.y + b1.y),
                            to_tf32(d6*rs*g1.z + b1.z), to_tf32(d7*rs*g1.w + b1.w));
    *(float4*)&y[base + tid * 4] = o0;
    *(float4*)&y[base + 1024 + tid * 4] = o1;
}

// ---------------- TF32 tensor-core GEMM, cp.async 3-stage pipeline ---------
// C[M,N] = A[M,K] @ W[K,N] (+bias)(+res)(+gelu->tf32). A, W pre-rounded tf32.
// CTA 128x128, K-tile 32, 8 warps 4(m)x2(n), warp tile 32x64 m16n8k8.
// SMEM per stage: A 128x36 floats (144B rows) + B 32x132 floats (528B rows)
//   = 18432 + 16896 = 35328 B. 3 stages = 105984 B dynamic.
#define STAGE_B 35328
#define STAGE_F 8832
#define GSMEM   105984

template<int ACT, int HASRES>
__global__ __launch_bounds__(256, 2) void gemm_cp(
    const float* __restrict__ A, const float* __restrict__ W,
    const float* __restrict__ bias, const float* __restrict__ res,
    float* __restrict__ C, int M, int N, int K)
{
    extern __shared__ float sm[];
    const uint32_t sb = smem_u32(sm);
    const int tid = threadIdx.x;
    const int warp = tid >> 5, lane = tid & 31;
    const int wm = warp >> 1, wn = warp & 1;
    const int g = lane >> 2, t4 = lane & 3;
    const int bm = blockIdx.y << 7, bn = blockIdx.x << 7;

    const float* Ab = A + (size_t)bm * K;
    const float* Wb = W + bn;
    const int KT = K >> 5;

    // per-thread chunk geometry
    const int ar = tid >> 3, ak = tid & 7;        // A: 4 chunks, rows ar+{0,32,64,96}
    const int br = tid >> 5, bc = tid & 31;       // B: 4 chunks, krows br+{0,8,16,24}

    float acc[2][8][4];
    #pragma unroll
    for (int a = 0; a < 2; a++)
        #pragma unroll
        for (int b2 = 0; b2 < 8; b2++)
            #pragma unroll
            for (int c = 0; c < 4; c++) acc[a][b2][c] = 0.f;

    // ---- async issue of k-tile kt into stage s ----
    auto issue = [&](int kt, int s) {
        const uint32_t st = sb + (uint32_t)s * STAGE_B;
        const int k0 = kt << 5;
        #pragma unroll
        for (int i = 0; i < 4; i++) {
            const int row = ar + (i << 5);
            cp16(st + row * 144 + ak * 16,
                 Ab + (size_t)row * K + k0 + (ak << 2));
        }
        #pragma unroll
        for (int i = 0; i < 4; i++) {
            const int kr = br + (i << 3);
            cp16(st + 18432 + kr * 528 + bc * 16,
                 Wb + (size_t)(k0 + kr) * N + (bc << 2));
        }
        asm volatile("cp.async.commit_group;" ::: "memory");
    };

    issue(0, 0);
    if (KT > 1) issue(1, 1);

    int s = 0;
    for (int kt = 0; kt < KT; kt++) {
        if (kt + 1 < KT) asm volatile("cp.async.wait_group 1;" ::: "memory");
        else             asm volatile("cp.async.wait_group 0;" ::: "memory");
        __syncthreads();
        if (kt + 2 < KT) {
            int ns = s + 2; if (ns >= 3) ns -= 3;
            issue(kt + 2, ns);
        }
        const float* As = sm + s * STAGE_F;          // [128][36]
        const float* Bs = As + 4608;                 // [32][132]

        #pragma unroll
        for (int ks = 0; ks < 4; ks++) {
            const int kb = ks << 3;
            uint32_t af[2][4], bf[8][2];
            #pragma unroll
            for (int mi = 0; mi < 2; mi++) {
                const int mr = (wm << 5) + (mi << 4);
                af[mi][0] = __float_as_uint(As[(mr + g    ) * 36 + kb + t4    ]);
                af[mi][1] = __float_as_uint(As[(mr + g + 8) * 36 + kb + t4    ]);
                af[mi][2] = __float_as_uint(As[(mr + g    ) * 36 + kb + t4 + 4]);
                af[mi][3] = __float_as_uint(As[(mr + g + 8) * 36 + kb + t4 + 4]);
            }
            #pragma unroll
            for (int ni = 0; ni < 8; ni++) {
                const int nc = (wn << 6) + (ni << 3) + g;
                bf[ni][0] = __float_as_uint(Bs[(kb + t4    ) * 132 + nc]);
                bf[ni][1] = __float_as_uint(Bs[(kb + t4 + 4) * 132 + nc]);
            }
            #pragma unroll
            for (int mi = 0; mi < 2; mi++)
                #pragma unroll
                for (int ni = 0; ni < 8; ni++)
                    mma8(acc[mi][ni], af[mi], bf[ni]);
        }
        __syncthreads();
        if (++s == 3) s = 0;
    }

    // epilogue: c0,c1 at (row, 2t4),(row, 2t4+1); c2,c3 at row+8
    #pragma unroll
    for (int mi = 0; mi < 2; mi++) {
        const int row0 = bm + (wm << 5) + (mi << 4) + g;
        #pragma unroll
        for (int ni = 0; ni < 8; ni++) {
            const int col = bn + (wn << 6) + (ni << 3) + (t4 << 1);
            const float b0 = bias[col], b1 = bias[col + 1];
            float v00 = acc[mi][ni][0] + b0, v01 = acc[mi][ni][1] + b1;
            float v10 = acc[mi][ni][2] + b0, v11 = acc[mi][ni][3] + b1;
            const size_t i0 = (size_t)row0 * N + col;
            const size_t i1 = i0 + (size_t)8 * N;
            if (HASRES) {
                v00 += res[i0]; v01 += res[i0 + 1];
                v10 += res[i1]; v11 += res[i1 + 1];
            }
            if (ACT == 1) {
                v00 = to_tf32(gelu_f(v00)); v01 = to_tf32(gelu_f(v01));
                v10 = to_tf32(gelu_f(v10)); v11 = to_tf32(gelu_f(v11));
            }
            *(float2*)&C[i0] = make_float2(v00, v01);
            *(float2*)&C[i1] = make_float2(v10, v11);
        }
    }
}

// ---------------- causal flash attention (fp32, online softmax) ------------
__global__ __launch_bounds__(256) void flash_kernel(
    const float* __restrict__ Q, const float* __restrict__ K,
    const float* __restrict__ V, float* __restrict__ O)
{
    extern __shared__ float smf[];
    float* QsT  = smf;           // [128][64]
    float* KsT  = smf + 8192;    // [128][64]
    float* Vs   = smf + 16384;   // [64][128]
    float* Ss   = smf + 24576;   // [64][64]
    float* mrow = smf + 28672;
    float* lrow = smf + 28736;
    float* arow = smf + 28800;

    const int tid = threadIdx.x;
    const int warp = tid >> 5, lane = tid & 31;
    const int b = blockIdx.y >> 4, h = blockIdx.y & 15;
    const int q0 = blockIdx.x << 6;
    const size_t base = ((size_t)b * 2048) * 2048 + (size_t)h * 128;
    const float* Qg = Q + base;
    const float* Kg = K + base;
    const float* Vg = V + base;
    float*       Og = O + base;

    {
        const int i = tid & 63, c = tid >> 6;
        #pragma unroll
        for (int l = 0; l < 8; l++) {
            const int k4 = (c << 3) + l;
            const float4 qv = *(const float4*)&Qg[(size_t)(q0 + i) * 2048 + (k4 << 2)];
            QsT[((k4 << 2) + 0) * 64 + i] = qv.x;
            QsT[((k4 << 2) + 1) * 64 + i] = qv.y;
            QsT[((k4 << 2) + 2) * 64 + i] = qv.z;
            QsT[((k4 << 2) + 3) * 64 + i] = qv.w;
        }
    }
    if (tid < 64) { mrow[tid] = -1e30f; lrow[tid] = 0.f; }

    float o[8][4];
    #pragma unroll
    for (int u = 0; u < 8; u++) { o[u][0] = 0; o[u][1] = 0; o[u][2] = 0; o[u][3] = 0; }

    const int ntile = (q0 >> 6) + 1;
    for (int kt = 0; kt < ntile; kt++) {
        const int k0 = kt << 6;
        __syncthreads();
        {
            const int i = tid & 63, c = tid >> 6;
            #pragma unroll
            for (int l = 0; l < 8; l++) {
                const int k4 = (c << 3) + l;
                const float4 kv = *(const float4*)&Kg[(size_t)(k0 + i) * 2048 + (k4 << 2)];
                KsT[((k4 << 2) + 0) * 64 + i] = kv.x;
                KsT[((k4 << 2) + 1) * 64 + i] = kv.y;
                KsT[((k4 << 2) + 2) * 64 + i] = kv.z;
                KsT[((k4 << 2) + 3) * 64 + i] = kv.w;
            }
        }
        #pragma unroll
        for (int rr = 0; rr < 8; rr++) {
            const int f4 = tid + (rr << 8);
            const int j = f4 >> 5, c4 = f4 & 31;
            *(float4*)&Vs[j * 128 + (c4 << 2)] =
                *(const float4*)&Vg[(size_t)(k0 + j) * 2048 + (c4 << 2)];
        }
        __syncthreads();

        {
            const int tr = tid >> 4, tc = tid & 15;
            float s[4][4];
            #pragma unroll
            for (int u = 0; u < 4; u++)
                #pragma unroll
                for (int v2 = 0; v2 < 4; v2++) s[u][v2] = 0.f;
            for (int kk = 0; kk < 128; kk++) {
                const float4 qv = *(const float4*)&QsT[kk * 64 + (tr << 2)];
                const float4 kv = *(const float4*)&KsT[kk * 64 + (tc << 2)];
                const float qa[4] = {qv.x, qv.y, qv.z, qv.w};
                const float ka[4] = {kv.x, kv.y, kv.z, kv.w};
                #pragma unroll
                for (int u = 0; u < 4; u++)
                    #pragma unroll
                    for (int v2 = 0; v2 < 4; v2++) s[u][v2] += qa[u] * ka[v2];
            }
            #pragma unroll
            for (int u = 0; u < 4; u++) {
                const int qi = (tr << 2) + u;
                #pragma unroll
                for (int v2 = 0; v2 < 4; v2++) {
                    const int kj = (tc << 2) + v2;
                    float val = s[u][v2] * 0.08838834764831845f;
                    if (k0 + kj > q0 + qi) val = -1e30f;
                    Ss[qi * 64 + kj] = val;
                }
            }
        }
        __syncthreads();

        {
            const int rid = tid >> 2, c0 = tid & 3;
            float mx = -1e30f;
            #pragma unroll
            for (int jc = c0; jc < 64; jc += 4) mx = fmaxf(mx, Ss[rid * 64 + jc]);
            mx = fmaxf(mx, __shfl_xor_sync(0xffffffffu, mx, 1));
            mx = fmaxf(mx, __shfl_xor_sync(0xffffffffu, mx, 2));
            const float mold = mrow[rid];
            const float mnew = fmaxf(mold, mx);
            float sum = 0.f;
            #pragma unroll
            for (int jc = c0; jc < 64; jc += 4) {
                const float p = __expf(Ss[rid * 64 + jc] - mnew);
                Ss[rid * 64 + jc] = p;
                sum += p;
            }
            sum += __shfl_xor_sync(0xffffffffu, sum, 1);
            sum += __shfl_xor_sync(0xffffffffu, sum, 2);
            if (c0 == 0) {
                arow[rid] = __expf(mold - mnew);
                lrow[rid] = lrow[rid] * arow[rid] + sum;
                mrow[rid] = mnew;
            }
        }
        __syncthreads();

        {
            #pragma unroll
            for (int u = 0; u < 8; u++) {
                const float al = arow[(warp << 3) + u];
                o[u][0] *= al; o[u][1] *= al; o[u][2] *= al; o[u][3] *= al;
            }
            for (int j = 0; j < 64; j++) {
                const float4 vv = *(const float4*)&Vs[j * 128 + (lane << 2)];
                #pragma unroll
                for (int u = 0; u < 8; u++) {
                    const float p = Ss[((warp << 3) + u) * 64 + j];
                    o[u][0] += p * vv.x; o[u][1] += p * vv.y;
                    o[u][2] += p * vv.z; o[u][3] += p * vv.w;
                }
            }
        }
    }

    #pragma unroll
    for (int u = 0; u < 8; u++) {
        const int r = (warp << 3) + u;
        const float inv = 1.0f / lrow[r];
        const float4 ov = make_float4(to_tf32(o[u][0] * inv), to_tf32(o[u][1] * inv),
                                      to_tf32(o[u][2] * inv), to_tf32(o[u][3] * inv));
        *(float4*)&Og[(size_t)(q0 + r) * 2048 + (lane << 2)] = ov;
    }
}

// ---------------- host orchestration ---------------------------------------
extern "C" void kernel_launch(void* const* d_in, const int* in_sizes, int n_in,
                              void* d_out, int out_size)
{
    const float* x     = (const float*)d_in[0];
    const float* ln1_g = (const float*)d_in[2];
    const float* ln1_b = (const float*)d_in[3];
    const float* wq    = (const float*)d_in[4];
    const float* bq    = (const float*)d_in[5];
    const float* wk    = (const float*)d_in[6];
    const float* bk    = (const float*)d_in[7];
    const float* wv    = (const float*)d_in[8];
    const float* bv    = (const float*)d_in[9];
    const float* wo    = (const float*)d_in[10];
    const float* bo    = (const float*)d_in[11];
    const float* ln2_g = (const float*)d_in[12];
    const float* ln2_b = (const float*)d_in[13];
    const float* w_in  = (const float*)d_in[14];
    const float* b_in  = (const float*)d_in[15];
    const float* w_out = (const float*)d_in[16];
    const float* b_out = (const float*)d_in[17];
    float* out = (float*)d_out;

    float *xn, *q, *k, *v, *attn, *x1, *h;
    float *wqr, *wkr, *wvr, *wor, *winr, *woutr;
    cudaGetSymbolAddress((void**)&xn,    g_xn);
    cudaGetSymbolAddress((void**)&q,     g_q);
    cudaGetSymbolAddress((void**)&k,     g_k);
    cudaGetSymbolAddress((void**)&v,     g_v);
    cudaGetSymbolAddress((void**)&attn,  g_attn);
    cudaGetSymbolAddress((void**)&x1,    g_x1);
    cudaGetSymbolAddress((void**)&h,     g_h);
    cudaGetSymbolAddress((void**)&wqr,   g_wqr);
    cudaGetSymbolAddress((void**)&wkr,   g_wkr);
    cudaGetSymbolAddress((void**)&wvr,   g_wvr);
    cudaGetSymbolAddress((void**)&wor,   g_wor);
    cudaGetSymbolAddress((void**)&winr,  g_winr);
    cudaGetSymbolAddress((void**)&woutr, g_woutr);

    cudaFuncSetAttribute(flash_kernel,
                         cudaFuncAttributeMaxDynamicSharedMemorySize, 115456);
    cudaFuncSetAttribute(gemm_cp<0,0>,
                         cudaFuncAttributeMaxDynamicSharedMemorySize, GSMEM);
    cudaFuncSetAttribute(gemm_cp<0,1>,
                         cudaFuncAttributeMaxDynamicSharedMemorySize, GSMEM);
    cudaFuncSetAttribute(gemm_cp<1,0>,
                         cudaFuncAttributeMaxDynamicSharedMemorySize, GSMEM);

    // weight tf32 pre-rounding (elementwise; layout unchanged [K,N])
    round_kernel<<<4096, 256>>>(wq,    wqr,   1048576);
    round_kernel<<<4096, 256>>>(wk,    wkr,   1048576);
    round_kernel<<<4096, 256>>>(wv,    wvr,   1048576);
    round_kernel<<<4096, 256>>>(wo,    wor,   1048576);
    round_kernel<<<16384, 256>>>(w_in,  winr,  4194304);
    round_kernel<<<16384, 256>>>(w_out, woutr, 4194304);

    const dim3 gD(16, 32);   // N=2048: (2048/128, 4096/128)
    const dim3 gF(64, 32);   // N=8192

    ln_kernel<<<4096, 256>>>(x, ln1_g, ln1_b, xn);
    gemm_cp<0,0><<<gD, 256, GSMEM>>>(xn, wqr, bq, nullptr, q, 4096, 2048, 2048);
    gemm_cp<0,0><<<gD, 256, GSMEM>>>(xn, wkr, bk, nullptr, k, 4096, 2048, 2048);
    gemm_cp<0,0><<<gD, 256, GSMEM>>>(xn, wvr, bv, nullptr, v, 4096, 2048, 2048);
    flash_kernel<<<dim3(32, 32), 256, 115456>>>(q, k, v, attn);
    gemm_cp<0,1><<<gD, 256, GSMEM>>>(attn, wor, bo, x, x1, 4096, 2048, 2048);
    ln_kernel<<<4096, 256>>>(x1, ln2_g, ln2_b, xn);
    gemm_cp<1,0><<<gF, 256, GSMEM>>>(xn, winr, b_in, nullptr, h, 4096, 8192, 2048);
    gemm_cp<0,1><<<gD, 256, GSMEM>>>(h, woutr, b_out, x1, out, 4096, 2048, 8192);
}

// round 4
// speedup vs baseline: 1.6485x; 1.4187x over previous
#include <cuda_runtime.h>
#include <cstdint>
#include <math.h>

// Problem dims: B=2, S=2048, D=2048, H=16, DH=128, DFF=8192
#define BSD 8388608   // B*S*D
#define BSF 33554432  // B*S*DFF

// ---------------- scratch (static device globals; no runtime allocation) ---
__device__ float g_xn[BSD];
__device__ float g_q[BSD];
__device__ float g_k[BSD];
__device__ float g_v[BSD];
__device__ float g_attn[BSD];
__device__ float g_x1[BSD];
__device__ float g_h[BSF];
// tf32-rounded weight copies (same [K,N] layout as inputs)
__device__ float g_wqr[4194304];
__device__ float g_wkr[4194304];
__device__ float g_wvr[4194304];
__device__ float g_wor[4194304];
__device__ float g_winr[16777216];
__device__ float g_woutr[16777216];

// ---------------- helpers --------------------------------------------------
__device__ __forceinline__ float to_tf32(float x) {
    float r; asm("cvt.rna.tf32.f32 %0, %1;" : "=f"(r) : "f"(x)); return r;
}
__device__ __forceinline__ uint32_t smem_u32(const void* p) {
    uint32_t a;
    asm("{ .reg .u64 t; cvta.to.shared.u64 t, %1; cvt.u32.u64 %0, t; }"
        : "=r"(a) : "l"(p));
    return a;
}
__device__ __forceinline__ void cp16(uint32_t s, const void* g) {
    asm volatile("cp.async.cg.shared.global [%0], [%1], 16;" :: "r"(s), "l"(g));
}
__device__ __forceinline__ void mma8(float* d, const uint32_t* a, const uint32_t* b) {
    asm volatile(
        "mma.sync.aligned.m16n8k8.row.col.f32.tf32.tf32.f32 "
        "{%0,%1,%2,%3}, {%4,%5,%6,%7}, {%8,%9}, {%0,%1,%2,%3};\n"
        : "+f"(d[0]), "+f"(d[1]), "+f"(d[2]), "+f"(d[3])
        : "r"(a[0]), "r"(a[1]), "r"(a[2]), "r"(a[3]), "r"(b[0]), "r"(b[1]));
}
__device__ __forceinline__ float gelu_f(float v) {
    return 0.5f * v * (1.0f + erff(v * 0.70710678118654752f));
}

// ---------------- weight tf32 rounding (elementwise, float4) ---------------
__global__ __launch_bounds__(256) void round_kernel(
    const float* __restrict__ w, float* __restrict__ o, int n4)
{
    const int i = blockIdx.x * 256 + threadIdx.x;
    if (i < n4) {
        const float4 v = *(const float4*)&w[(size_t)i * 4];
        *(float4*)&o[(size_t)i * 4] =
            make_float4(to_tf32(v.x), to_tf32(v.y), to_tf32(v.z), to_tf32(v.w));
    }
}

// ---------------- block reduce ---------------------------------------------
__device__ __forceinline__ float block_sum256(float v) {
    __shared__ float red[8];
    #pragma unroll
    for (int o = 16; o; o >>= 1) v += __shfl_xor_sync(0xffffffffu, v, o);
    const int w = threadIdx.x >> 5, l = threadIdx.x & 31;
    __syncthreads();
    if (l == 0) red[w] = v;
    __syncthreads();
    float t = red[l & 7];
    t += __shfl_xor_sync(0xffffffffu, t, 1);
    t += __shfl_xor_sync(0xffffffffu, t, 2);
    t += __shfl_xor_sync(0xffffffffu, t, 4);
    return t;
}

// ---------------- LayerNorm (tf32-rounded output) --------------------------
__global__ __launch_bounds__(256) void ln_kernel(
    const float* __restrict__ x, const float* __restrict__ gw,
    const float* __restrict__ bw, float* __restrict__ y)
{
    const size_t base = (size_t)blockIdx.x * 2048;
    const int tid = threadIdx.x;
    const float4 v0 = *(const float4*)&x[base + tid * 4];
    const float4 v1 = *(const float4*)&x[base + 1024 + tid * 4];

    float s = v0.x + v0.y + v0.z + v0.w + v1.x + v1.y + v1.z + v1.w;
    const float mean = block_sum256(s) * (1.0f / 2048.0f);

    const float d0 = v0.x - mean, d1 = v0.y - mean, d2 = v0.z - mean, d3 = v0.w - mean;
    const float d4 = v1.x - mean, d5 = v1.y - mean, d6 = v1.z - mean, d7 = v1.w - mean;
    float q = d0*d0 + d1*d1 + d2*d2 + d3*d3 + d4*d4 + d5*d5 + d6*d6 + d7*d7;
    const float var = block_sum256(q) * (1.0f / 2048.0f);
    const float rs = rsqrtf(var + 1e-5f);

    const float4 g0 = *(const float4*)&gw[tid * 4];
    const float4 g1 = *(const float4*)&gw[1024 + tid * 4];
    const float4 b0 = *(const float4*)&bw[tid * 4];
    const float4 b1 = *(const float4*)&bw[1024 + tid * 4];

    float4 o0 = make_float4(to_tf32(d0*rs*g0.x + b0.x), to_tf32(d1*rs*g0.y + b0.y),
                            to_tf32(d2*rs*g0.z + b0.z), to_tf32(d3*rs*g0.w + b0.w));
    float4 o1 = make_float4(to_tf32(d4*rs*g1.x + b1.x), to_tf32(d5*rs*g1.y + b1.y),
                            to_tf32(d6*rs*g1.z + b1.z), to_tf32(d7*rs*g1.w + b1.w));
    *(float4*)&y[base + tid * 4] = o0;
    *(float4*)&y[base + 1024 + tid * 4] = o1;
}

// ---------------- TF32 tensor-core GEMM, cp.async 3-stage pipeline ---------
// C[M,N] = A[M,K] @ W[K,N] (+bias)(+res)(+gelu)(+tf32 round). Pre-rounded in.
// CTA 128x128, K-tile 32, 8 warps 4(m)x2(n), warp tile 32x64 m16n8k8.
// SMEM per stage: A 128x36 f (144B rows, bank=4m+k) +
//                 B 32x136 f (544B rows, bank=8k+n)  — both conflict-free.
//   stage = 18432 + 17408 = 35840 B; 3 stages = 107520 B dynamic.
#define STAGE_B 35840
#define STAGE_F 8960
#define GSMEM   107520

template<int ACT, int HASRES, int RND>
__global__ __launch_bounds__(256, 2) void gemm_cp(
    const float* __restrict__ A, const float* __restrict__ W,
    const float* __restrict__ bias, const float* __restrict__ res,
    float* __restrict__ C, int M, int N, int K)
{
    extern __shared__ float sm[];
    const uint32_t sb = smem_u32(sm);
    const int tid = threadIdx.x;
    const int warp = tid >> 5, lane = tid & 31;
    const int wm = warp >> 1, wn = warp & 1;
    const int g = lane >> 2, t4 = lane & 3;
    const int bm = blockIdx.y << 7, bn = blockIdx.x << 7;

    const float* Ab = A + (size_t)bm * K;
    const float* Wb = W + bn;
    const int KT = K >> 5;

    const int ar = tid >> 3, ak = tid & 7;        // A: rows ar+{0,32,64,96}
    const int br = tid >> 5, bc = tid & 31;       // B: krows br+{0,8,16,24}

    float acc[2][8][4];
    #pragma unroll
    for (int a = 0; a < 2; a++)
        #pragma unroll
        for (int b2 = 0; b2 < 8; b2++)
            #pragma unroll
            for (int c = 0; c < 4; c++) acc[a][b2][c] = 0.f;

    auto issue = [&](int kt, int s) {
        const uint32_t st = sb + (uint32_t)s * STAGE_B;
        const int k0 = kt << 5;
        #pragma unroll
        for (int i = 0; i < 4; i++) {
            const int row = ar + (i << 5);
            cp16(st + row * 144 + ak * 16,
                 Ab + (size_t)row * K + k0 + (ak << 2));
        }
        #pragma unroll
        for (int i = 0; i < 4; i++) {
            const int kr = br + (i << 3);
            cp16(st + 18432 + kr * 544 + bc * 16,
                 Wb + (size_t)(k0 + kr) * N + (bc << 2));
        }
        asm volatile("cp.async.commit_group;" ::: "memory");
    };

    issue(0, 0);
    if (KT > 1) issue(1, 1);

    int s = 0;
    for (int kt = 0; kt < KT; kt++) {
        if (kt + 1 < KT) asm volatile("cp.async.wait_group 1;" ::: "memory");
        else             asm volatile("cp.async.wait_group 0;" ::: "memory");
        __syncthreads();
        if (kt + 2 < KT) {
            int ns = s + 2; if (ns >= 3) ns -= 3;
            issue(kt + 2, ns);
        }
        const float* As = sm + s * STAGE_F;          // [128][36]
        const float* Bs = As + 4608;                 // [32][136]

        #pragma unroll
        for (int ks = 0; ks < 4; ks++) {
            const int kb = ks << 3;
            uint32_t af[2][4];
            #pragma unroll
            for (int mi = 0; mi < 2; mi++) {
                const int mr = (wm << 5) + (mi << 4);
                af[mi][0] = __float_as_uint(As[(mr + g    ) * 36 + kb + t4    ]);
                af[mi][1] = __float_as_uint(As[(mr + g + 8) * 36 + kb + t4    ]);
                af[mi][2] = __float_as_uint(As[(mr + g    ) * 36 + kb + t4 + 4]);
                af[mi][3] = __float_as_uint(As[(mr + g + 8) * 36 + kb + t4 + 4]);
            }
            #pragma unroll
            for (int ni = 0; ni < 8; ni++) {
                const int nc = (wn << 6) + (ni << 3) + g;
                uint32_t bf[2];
                bf[0] = __float_as_uint(Bs[(kb + t4    ) * 136 + nc]);
                bf[1] = __float_as_uint(Bs[(kb + t4 + 4) * 136 + nc]);
                mma8(acc[0][ni], af[0], bf);
                mma8(acc[1][ni], af[1], bf);
            }
        }
        __syncthreads();
        if (++s == 3) s = 0;
    }

    // epilogue
    #pragma unroll
    for (int mi = 0; mi < 2; mi++) {
        const int row0 = bm + (wm << 5) + (mi << 4) + g;
        #pragma unroll
        for (int ni = 0; ni < 8; ni++) {
            const int col = bn + (wn << 6) + (ni << 3) + (t4 << 1);
            const float b0 = bias[col], b1 = bias[col + 1];
            float v00 = acc[mi][ni][0] + b0, v01 = acc[mi][ni][1] + b1;
            float v10 = acc[mi][ni][2] + b0, v11 = acc[mi][ni][3] + b1;
            const size_t i0 = (size_t)row0 * N + col;
            const size_t i1 = i0 + (size_t)8 * N;
            if (HASRES) {
                v00 += res[i0]; v01 += res[i0 + 1];
                v10 += res[i1]; v11 += res[i1 + 1];
            }
            if (ACT == 1) {
                v00 = to_tf32(gelu_f(v00)); v01 = to_tf32(gelu_f(v01));
                v10 = to_tf32(gelu_f(v10)); v11 = to_tf32(gelu_f(v11));
            } else if (RND) {
                v00 = to_tf32(v00); v01 = to_tf32(v01);
                v10 = to_tf32(v10); v11 = to_tf32(v11);
            }
            *(float2*)&C[i0] = make_float2(v00, v01);
            *(float2*)&C[i1] = make_float2(v10, v11);
        }
    }
}

// ---------------- causal flash attention (tf32 mma, online softmax) --------
// 64 q-rows per CTA, 64-wide k-tiles, DH=128. 8 warps, 256 threads.
// QK^T: S[64,64] = Q[64,128] @ K[64,128]^T  (A=Q row-major, B=K row-major)
// PV:   O^T[128,64] = V^T[128,64k] @ P^T    (A[m=d][k]=Vs[k][d], B[k][n=q]=Ss[q][k])
// smem (floats): Qs[64][132], Ks[64][132], Vs[64][132], Ss[64][68], m/l/a[64]
#define FSMEM 119552

__global__ __launch_bounds__(256) void flash_kernel(
    const float* __restrict__ Q, const float* __restrict__ K,
    const float* __restrict__ V, float* __restrict__ O)
{
    extern __shared__ float smf[];
    float* Qs   = smf;                 // [64][132]
    float* Ks   = smf + 8448;          // [64][132]
    float* Vs   = smf + 16896;         // [64][132]
    float* Ss   = smf + 25344;         // [64][68]
    float* mrow = smf + 29696;
    float* lrow = smf + 29760;
    float* arow = smf + 29824;

    const int tid = threadIdx.x;
    const int warp = tid >> 5, lane = tid & 31;
    const int g = lane >> 2, t4 = lane & 3;
    const int wm = warp >> 1, wn = warp & 1;    // S: 4(m)x2(n); PV: 4(d)x2(q)
    const int b = blockIdx.y >> 4, h = blockIdx.y & 15;
    const int q0 = blockIdx.x << 6;
    const size_t base = ((size_t)b * 2048) * 2048 + (size_t)h * 128;
    const float* Qg = Q + base;
    const float* Kg = K + base;
    const float* Vg = V + base;
    float*       Og = O + base;

    // load Q tile row-major
    #pragma unroll
    for (int rr = 0; rr < 8; rr++) {
        const int f4 = tid + (rr << 8);
        const int row = f4 >> 5, c4 = f4 & 31;
        *(float4*)&Qs[row * 132 + (c4 << 2)] =
            *(const float4*)&Qg[(size_t)(q0 + row) * 2048 + (c4 << 2)];
    }
    if (tid < 64) { mrow[tid] = -1e30f; lrow[tid] = 0.f; }

    float o[2][4][4];
    #pragma unroll
    for (int mi = 0; mi < 2; mi++)
        #pragma unroll
        for (int ni = 0; ni < 4; ni++)
            #pragma unroll
            for (int c = 0; c < 4; c++) o[mi][ni][c] = 0.f;

    const int ntile = (q0 >> 6) + 1;
    for (int kt = 0; kt < ntile; kt++) {
        const int k0 = kt << 6;
        __syncthreads();   // prev PV done; Q store/init done (first iter)
        #pragma unroll
        for (int rr = 0; rr < 8; rr++) {
            const int f4 = tid + (rr << 8);
            const int row = f4 >> 5, c4 = f4 & 31;
            *(float4*)&Ks[row * 132 + (c4 << 2)] =
                *(const float4*)&Kg[(size_t)(k0 + row) * 2048 + (c4 << 2)];
            *(float4*)&Vs[row * 132 + (c4 << 2)] =
                *(const float4*)&Vg[(size_t)(k0 + row) * 2048 + (c4 << 2)];
        }
        __syncthreads();

        // ---- S = Q K^T (warp tile 16x32) ----
        {
            float sacc[4][4];
            #pragma unroll
            for (int ni = 0; ni < 4; ni++)
                #pragma unroll
                for (int c = 0; c < 4; c++) sacc[ni][c] = 0.f;
            const int m0 = wm << 4;
            #pragma unroll
            for (int kk = 0; kk < 16; kk++) {
                const int kb = kk << 3;
                uint32_t af[4];
                af[0] = __float_as_uint(Qs[(m0 + g    ) * 132 + kb + t4    ]);
                af[1] = __float_as_uint(Qs[(m0 + g + 8) * 132 + kb + t4    ]);
                af[2] = __float_as_uint(Qs[(m0 + g    ) * 132 + kb + t4 + 4]);
                af[3] = __float_as_uint(Qs[(m0 + g + 8) * 132 + kb + t4 + 4]);
                #pragma unroll
                for (int ni = 0; ni < 4; ni++) {
                    const int n = (wn << 5) + (ni << 3) + g;
                    uint32_t bf[2];
                    bf[0] = __float_as_uint(Ks[n * 132 + kb + t4    ]);
                    bf[1] = __float_as_uint(Ks[n * 132 + kb + t4 + 4]);
                    mma8(sacc[ni], af, bf);
                }
            }
            // write S with scale + causal mask
            #pragma unroll
            for (int ni = 0; ni < 4; ni++) {
                const int col = (wn << 5) + (ni << 3) + (t4 << 1);
                const int r0 = m0 + g, r1 = m0 + g + 8;
                float v00 = sacc[ni][0] * 0.08838834764831845f;
                float v01 = sacc[ni][1] * 0.08838834764831845f;
                float v10 = sacc[ni][2] * 0.08838834764831845f;
                float v11 = sacc[ni][3] * 0.08838834764831845f;
                if (k0 + col     > q0 + r0) v00 = -1e30f;
                if (k0 + col + 1 > q0 + r0) v01 = -1e30f;
                if (k0 + col     > q0 + r1) v10 = -1e30f;
                if (k0 + col + 1 > q0 + r1) v11 = -1e30f;
                Ss[r0 * 68 + col] = v00; Ss[r0 * 68 + col + 1] = v01;
                Ss[r1 * 68 + col] = v10; Ss[r1 * 68 + col + 1] = v11;
            }
        }
        __syncthreads();

        // ---- online softmax (4 threads per row); P stored tf32-rounded ----
        {
            const int rid = tid >> 2, c0 = tid & 3;
            float mx = -1e30f;
            #pragma unroll
            for (int jc = c0; jc < 64; jc += 4) mx = fmaxf(mx, Ss[rid * 68 + jc]);
            mx = fmaxf(mx, __shfl_xor_sync(0xffffffffu, mx, 1));
            mx = fmaxf(mx, __shfl_xor_sync(0xffffffffu, mx, 2));
            const float mold = mrow[rid];
            const float mnew = fmaxf(mold, mx);
            float sum = 0.f;
            #pragma unroll
            for (int jc = c0; jc < 64; jc += 4) {
                const float p = to_tf32(__expf(Ss[rid * 68 + jc] - mnew));
                Ss[rid * 68 + jc] = p;
                sum += p;
            }
            sum += __shfl_xor_sync(0xffffffffu, sum, 1);
            sum += __shfl_xor_sync(0xffffffffu, sum, 2);
            if (c0 == 0) {
                arow[rid] = __expf(mold - mnew);
                lrow[rid] = lrow[rid] * arow[rid] + sum;
                mrow[rid] = mnew;
            }
        }
        __syncthreads();

        // ---- O^T += V^T @ P^T (warp tile 32d x 32q) ----
        {
            const int d0 = wm << 5, qw = wn << 5;
            #pragma unroll
            for (int ni = 0; ni < 4; ni++) {
                const int cq = qw + (ni << 3) + (t4 << 1);
                const float a0 = arow[cq], a1 = arow[cq + 1];
                #pragma unroll
                for (int mi = 0; mi < 2; mi++) {
                    o[mi][ni][0] *= a0; o[mi][ni][1] *= a1;
                    o[mi][ni][2] *= a0; o[mi][ni][3] *= a1;
                }
            }
            #pragma unroll
            for (int k_ = 0; k_ < 8; k_++) {
                const int kb = k_ << 3;
                uint32_t af[2][4];
                #pragma unroll
                for (int mi = 0; mi < 2; mi++) {
                    const int dm = d0 + (mi << 4);
                    af[mi][0] = __float_as_uint(Vs[(kb + t4    ) * 132 + dm + g    ]);
                    af[mi][1] = __float_as_uint(Vs[(kb + t4    ) * 132 + dm + g + 8]);
                    af[mi][2] = __float_as_uint(Vs[(kb + t4 + 4) * 132 + dm + g    ]);
                    af[mi][3] = __float_as_uint(Vs[(kb + t4 + 4) * 132 + dm + g + 8]);
                }
                #pragma unroll
                for (int ni = 0; ni < 4; ni++) {
                    const int nq = qw + (ni << 3) + g;
                    uint32_t bf[2];
                    bf[0] = __float_as_uint(Ss[nq * 68 + kb + t4    ]);
                    bf[1] = __float_as_uint(Ss[nq * 68 + kb + t4 + 4]);
                    mma8(o[0][ni], af[0], bf);
                    mma8(o[1][ni], af[1], bf);
                }
            }
        }
    }

    // ---- normalize + store O[q][d] (acc holds O^T) ----
    __syncthreads();
    {
        const int d0 = wm << 5, qw = wn << 5;
        #pragma unroll
        for (int ni = 0; ni < 4; ni++) {
            const int cq = qw + (ni << 3) + (t4 << 1);
            const float inv0 = 1.0f / lrow[cq], inv1 = 1.0f / lrow[cq + 1];
            #pragma unroll
            for (int mi = 0; mi < 2; mi++) {
                const int d = d0 + (mi << 4) + g;
                Og[(size_t)(q0 + cq    ) * 2048 + d    ] = to_tf32(o[mi][ni][0] * inv0);
                Og[(size_t)(q0 + cq + 1) * 2048 + d    ] = to_tf32(o[mi][ni][1] * inv1);
                Og[(size_t)(q0 + cq    ) * 2048 + d + 8] = to_tf32(o[mi][ni][2] * inv0);
                Og[(size_t)(q0 + cq + 1) * 2048 + d + 8] = to_tf32(o[mi][ni][3] * inv1);
            }
        }
    }
}

// ---------------- host orchestration ---------------------------------------
extern "C" void kernel_launch(void* const* d_in, const int* in_sizes, int n_in,
                              void* d_out, int out_size)
{
    const float* x     = (const float*)d_in[0];
    const float* ln1_g = (const float*)d_in[2];
    const float* ln1_b = (const float*)d_in[3];
    const float* wq    = (const float*)d_in[4];
    const float* bq    = (const float*)d_in[5];
    const float* wk    = (const float*)d_in[6];
    const float* bk    = (const float*)d_in[7];
    const float* wv    = (const float*)d_in[8];
    const float* bv    = (const float*)d_in[9];
    const float* wo    = (const float*)d_in[10];
    const float* bo    = (const float*)d_in[11];
    const float* ln2_g = (const float*)d_in[12];
    const float* ln2_b = (const float*)d_in[13];
    const float* w_in  = (const float*)d_in[14];
    const float* b_in  = (const float*)d_in[15];
    const float* w_out = (const float*)d_in[16];
    const float* b_out = (const float*)d_in[17];
    float* out = (float*)d_out;

    float *xn, *q, *k, *v, *attn, *x1, *h;
    float *wqr, *wkr, *wvr, *wor, *winr, *woutr;
    cudaGetSymbolAddress((void**)&xn,    g_xn);
    cudaGetSymbolAddress((void**)&q,     g_q);
    cudaGetSymbolAddress((void**)&k,     g_k);
    cudaGetSymbolAddress((void**)&v,     g_v);
    cudaGetSymbolAddress((void**)&attn,  g_attn);
    cudaGetSymbolAddress((void**)&x1,    g_x1);
    cudaGetSymbolAddress((void**)&h,     g_h);
    cudaGetSymbolAddress((void**)&wqr,   g_wqr);
    cudaGetSymbolAddress((void**)&wkr,   g_wkr);
    cudaGetSymbolAddress((void**)&wvr,   g_wvr);
    cudaGetSymbolAddress((void**)&wor,   g_wor);
    cudaGetSymbolAddress((void**)&winr,  g_winr);
    cudaGetSymbolAddress((void**)&woutr, g_woutr);

    cudaFuncSetAttribute(flash_kernel,
                         cudaFuncAttributeMaxDynamicSharedMemorySize, FSMEM);
    cudaFuncSetAttribute(gemm_cp<0,0,1>,
                         cudaFuncAttributeMaxDynamicSharedMemorySize, GSMEM);
    cudaFuncSetAttribute(gemm_cp<0,1,0>,
                         cudaFuncAttributeMaxDynamicSharedMemorySize, GSMEM);
    cudaFuncSetAttribute(gemm_cp<1,0,0>,
                         cudaFuncAttributeMaxDynamicSharedMemorySize, GSMEM);

    // weight tf32 pre-rounding (layout unchanged [K,N])
    round_kernel<<<4096, 256>>>(wq,    wqr,   1048576);
    round_kernel<<<4096, 256>>>(wk,    wkr,   1048576);
    round_kernel<<<4096, 256>>>(wv,    wvr,   1048576);
    round_kernel<<<4096, 256>>>(wo,    wor,   1048576);
    round_kernel<<<16384, 256>>>(w_in,  winr,  4194304);
    round_kernel<<<16384, 256>>>(w_out, woutr, 4194304);

    const dim3 gD(16, 32);   // N=2048
    const dim3 gF(64, 32);   // N=8192

    ln_kernel<<<4096, 256>>>(x, ln1_g, ln1_b, xn);
    gemm_cp<0,0,1><<<gD, 256, GSMEM>>>(xn, wqr, bq, nullptr, q, 4096, 2048, 2048);
    gemm_cp<0,0,1><<<gD, 256, GSMEM>>>(xn, wkr, bk, nullptr, k, 4096, 2048, 2048);
    gemm_cp<0,0,1><<<gD, 256, GSMEM>>>(xn, wvr, bv, nullptr, v, 4096, 2048, 2048);
    flash_kernel<<<dim3(32, 32), 256, FSMEM>>>(q, k, v, attn);
    gemm_cp<0,1,0><<<gD, 256, GSMEM>>>(attn, wor, bo, x, x1, 4096, 2048, 2048);
    ln_kernel<<<4096, 256>>>(x1, ln2_g, ln2_b, xn);
    gemm_cp<1,0,0><<<gF, 256, GSMEM>>>(xn, winr, b_in, nullptr, h, 4096, 8192, 2048);
    gemm_cp<0,1,0><<<gD, 256, GSMEM>>>(h, woutr, b_out, x1, out, 4096, 2048, 8192);
}

// round 6
// speedup vs baseline: 1.7178x; 1.0420x over previous
#include <cuda_runtime.h>
#include <cstdint>
#include <math.h>

// Problem dims: B=2, S=2048, D=2048, H=16, DH=128, DFF=8192
#define BSD 8388608   // B*S*D
#define BSF 33554432  // B*S*DFF

// ---------------- scratch (static device globals; no runtime allocation) ---
__device__ float g_xn[BSD];         // LN out (k-permuted along D)
__device__ float g_qkv[25165824];   // [4096][6144] q|k|v
__device__ float g_attn[BSD];       // flash out (k-permuted along D)
__device__ float g_x1[BSD];
__device__ float g_h[BSF];          // gelu out (k-permuted along DFF)
// transposed [N,K] + tf32-rounded + k-permuted weights
__device__ float g_wqkvt[12582912]; // [6144][2048]
__device__ float g_wot[4194304];    // [2048][2048]
__device__ float g_wint[16777216];  // [8192][2048]
__device__ float g_woutt[16777216]; // [2048][8192]
__device__ float g_bqkv[6144];

// ---------------- helpers --------------------------------------------------
__device__ __forceinline__ float to_tf32(float x) {
    float r; asm("cvt.rna.tf32.f32 %0, %1;" : "=f"(r) : "f"(x)); return r;
}
__device__ __forceinline__ uint32_t smem_u32(const void* p) {
    uint32_t a;
    asm("{ .reg .u64 t; cvta.to.shared.u64 t, %1; cvt.u32.u64 %0, t; }"
        : "=r"(a) : "l"(p));
    return a;
}
__device__ __forceinline__ void cp16(uint32_t s, const void* g) {
    asm volatile("cp.async.cg.shared.global [%0], [%1], 16;" :: "r"(s), "l"(g));
}
__device__ __forceinline__ void mma8(float* d, const uint32_t* a, const uint32_t* b) {
    asm volatile(
        "mma.sync.aligned.m16n8k8.row.col.f32.tf32.tf32.f32 "
        "{%0,%1,%2,%3}, {%4,%5,%6,%7}, {%8,%9}, {%0,%1,%2,%3};\n"
        : "+f"(d[0]), "+f"(d[1]), "+f"(d[2]), "+f"(d[3])
        : "r"(a[0]), "r"(a[1]), "r"(a[2]), "r"(a[3]), "r"(b[0]), "r"(b[1]));
}
__device__ __forceinline__ float gelu_f(float v) {
    return 0.5f * v * (1.0f + erff(v * 0.70710678118654752f));
}
// k-permutation within 8-groups: logical l -> phys (l<4 ? 2l : 2(l-4)+1)
__device__ __forceinline__ int permc(int x) {   // x in 0..31, permute low 3 bits
    const int l = x & 7;
    return (x & 24) | ((l < 4) ? (l << 1) : (((l - 4) << 1) | 1));
}

// ---------------- weight prep: transpose [K,N]->[N,K], round, k-permute ----
__device__ void tp_tile(const float* __restrict__ src, float* __restrict__ dst,
                        int K, int N, int t)
{
    __shared__ float tbuf[32][33];
    const int tn = N >> 5;
    const int n0 = (t % tn) << 5, k0 = (t / tn) << 5;
    const int x = threadIdx.x & 31, y = threadIdx.x >> 5;
    #pragma unroll
    for (int i = 0; i < 32; i += 8)
        tbuf[y + i][x] = src[(size_t)(k0 + y + i) * N + n0 + x];
    __syncthreads();
    const int kp = k0 + permc(x);
    #pragma unroll
    for (int i = 0; i < 32; i += 8)
        dst[(size_t)(n0 + y + i) * K + kp] = to_tf32(tbuf[x][y + i]);
}

__global__ __launch_bounds__(256) void prep_a(
    const float* __restrict__ wq, const float* __restrict__ wk,
    const float* __restrict__ wv, const float* __restrict__ bq,
    const float* __restrict__ bk, const float* __restrict__ bv)
{
    const int blk = blockIdx.x;
    if (blk < 12288) {
        const int w = blk >> 12, t = blk & 4095;
        const float* src = (w == 0) ? wq : (w == 1) ? wk : wv;
        tp_tile(src, g_wqkvt + (size_t)w * 4194304, 2048, 2048, t);
    } else {
        const int idx = ((blk - 12288) << 8) + threadIdx.x;
        if (idx < 6144) {
            const int sel = idx >> 11;
            const float* b = (sel == 0) ? bq : (sel == 1) ? bk : bv;
            g_bqkv[idx] = b[idx & 2047];
        }
    }
}

__global__ __launch_bounds__(256) void prep_b(
    const float* __restrict__ wo, const float* __restrict__ w_in,
    const float* __restrict__ w_out)
{
    const int blk = blockIdx.x;
    if (blk < 4096)        tp_tile(wo,    g_wot,   2048, 2048, blk);
    else if (blk < 20480)  tp_tile(w_in,  g_wint,  2048, 8192, blk - 4096);
    else                   tp_tile(w_out, g_woutt, 8192, 2048, blk - 20480);
}

// ---------------- block reduce ---------------------------------------------
__device__ __forceinline__ float block_sum256(float v) {
    __shared__ float red[8];
    #pragma unroll
    for (int o = 16; o; o >>= 1) v += __shfl_xor_sync(0xffffffffu, v, o);
    const int w = threadIdx.x >> 5, l = threadIdx.x & 31;
    __syncthreads();
    if (l == 0) red[w] = v;
    __syncthreads();
    float t = red[l & 7];
    t += __shfl_xor_sync(0xffffffffu, t, 1);
    t += __shfl_xor_sync(0xffffffffu, t, 2);
    t += __shfl_xor_sync(0xffffffffu, t, 4);
    return t;
}

// ---------------- LayerNorm (tf32-rounded, k-permuted output) --------------
__global__ __launch_bounds__(256) void ln_kernel(
    const float* __restrict__ x, const float* __restrict__ gw,
    const float* __restrict__ bw, float* __restrict__ y)
{
    const size_t base = (size_t)blockIdx.x * 2048;
    const int c0 = threadIdx.x << 3;          // this thread owns cols c0..c0+7
    const float4 v0 = *(const float4*)&x[base + c0];
    const float4 v1 = *(const float4*)&x[base + c0 + 4];

    float s = v0.x + v0.y + v0.z + v0.w + v1.x + v1.y + v1.z + v1.w;
    const float mean = block_sum256(s) * (1.0f / 2048.0f);

    float d[8];
    d[0] = v0.x - mean; d[1] = v0.y - mean; d[2] = v0.z - mean; d[3] = v0.w - mean;
    d[4] = v1.x - mean; d[5] = v1.y - mean; d[6] = v1.z - mean; d[7] = v1.w - mean;
    float q = 0.f;
    #pragma unroll
    for (int i = 0; i < 8; i++) q += d[i] * d[i];
    const float var = block_sum256(q) * (1.0f / 2048.0f);
    const float rs = rsqrtf(var + 1e-5f);

    const float4 g0 = *(const float4*)&gw[c0];
    const float4 g1 = *(const float4*)&gw[c0 + 4];
    const float4 b0 = *(const float4*)&bw[c0];
    const float4 b1 = *(const float4*)&bw[c0 + 4];
    const float ga[8] = {g0.x, g0.y, g0.z, g0.w, g1.x, g1.y, g1.z, g1.w};
    const float ba[8] = {b0.x, b0.y, b0.z, b0.w, b1.x, b1.y, b1.z, b1.w};

    float o[8];
    #pragma unroll
    for (int i = 0; i < 8; i++) o[i] = to_tf32(d[i] * rs * ga[i] + ba[i]);

    // permuted write: phys (2i, 2i+1) = logical (i, i+4)
    #pragma unroll
    for (int i = 0; i < 4; i++)
        *(float2*)&y[base + c0 + (i << 1)] = make_float2(o[i], o[i + 4]);
}

// ---------------- TF32 GEMM: vectorized frags, XOR swizzle, 3-stage --------
// C[M,N] = A[M,K] @ Wt[N,K]^T (+bias)(+res)(+gelu)(rnd). A,Wt k-permuted.
// CTA 128x128, K-tile 32, 8 warps 4(m)x2(n), warp tile 32x64 m16n8k8.
// smem stage: A[128][32] + B[128][32] XOR-swizzled = 32KB; 3 stages = 96KB.
#define GSMEM 98304

template<int ACT, int HASRES, int RND, int PERMC>
__global__ __launch_bounds__(256, 2) void gemm_cp(
    const float* __restrict__ A, const float* __restrict__ Wt,
    const float* __restrict__ bias, const float* __restrict__ res,
    float* __restrict__ C, int M, int N, int K)
{
    extern __shared__ float sm[];
    const uint32_t sb = smem_u32(sm);
    const int tid = threadIdx.x;
    const int warp = tid >> 5, lane = tid & 31;
    const int wm = warp >> 1, wn = warp & 1;
    const int g = lane >> 2, t4 = lane & 3;
    const int bm = blockIdx.y << 7, bn = blockIdx.x << 7;

    const float* Ab = A  + (size_t)bm * K;
    const float* Bb = Wt + (size_t)bn * K;
    const int KT = K >> 5;

    // copy geometry: thread covers rows r0+32i, k-chunk cc (4 floats)
    const int r0 = tid >> 3;
    const int cc = (tid & 7) << 2;
    const uint32_t dcol = (uint32_t)((cc ^ ((r0 & 3) << 3)) << 2);  // bytes

    float acc[2][8][4];
    #pragma unroll
    for (int a = 0; a < 2; a++)
        #pragma unroll
        for (int b2 = 0; b2 < 8; b2++)
            #pragma unroll
            for (int c = 0; c < 4; c++) acc[a][b2][c] = 0.f;

    auto issue = [&](int kt, int s) {
        const uint32_t st = sb + (uint32_t)s * 32768u;
        const int k0 = kt << 5;
        #pragma unroll
        for (int i = 0; i < 4; i++) {
            const int row = r0 + (i << 5);
            cp16(st + row * 128 + dcol, Ab + (size_t)row * K + k0 + cc);
        }
        #pragma unroll
        for (int i = 0; i < 4; i++) {
            const int n = r0 + (i << 5);
            cp16(st + 16384 + n * 128 + dcol, Bb + (size_t)n * K + k0 + cc);
        }
        asm volatile("cp.async.commit_group;" ::: "memory");
    };

    issue(0, 0);
    if (KT > 1) issue(1, 1);

    const int swz = (g & 3) << 3;
    int s = 0;
    for (int kt = 0; kt < KT; kt++) {
        if (kt + 1 < KT) asm volatile("cp.async.wait_group 1;" ::: "memory");
        else             asm volatile("cp.async.wait_group 0;" ::: "memory");
        __syncthreads();
        if (kt + 2 < KT) {
            int ns = s + 2; if (ns >= 3) ns -= 3;
            issue(kt + 2, ns);
        }
        const float* As = sm + s * 8192;
        const float* Bs = As + 4096;

        #pragma unroll
        for (int ks = 0; ks < 4; ks++) {
            const int kc = ((ks << 3) + (t4 << 1)) ^ swz;
            uint32_t af[2][4];
            #pragma unroll
            for (int mi = 0; mi < 2; mi++) {
                const int mr = (wm << 5) + (mi << 4) + g;
                const float2 a02 = *(const float2*)&As[mr * 32 + kc];
                const float2 a13 = *(const float2*)&As[(mr + 8) * 32 + kc];
                af[mi][0] = __float_as_uint(a02.x);
                af[mi][1] = __float_as_uint(a13.x);
                af[mi][2] = __float_as_uint(a02.y);
                af[mi][3] = __float_as_uint(a13.y);
            }
            #pragma unroll
            for (int ni = 0; ni < 8; ni++) {
                const int nc = (wn << 6) + (ni << 3) + g;
                const float2 b01 = *(const float2*)&Bs[nc * 32 + kc];
                uint32_t bf[2];
                bf[0] = __float_as_uint(b01.x);
                bf[1] = __float_as_uint(b01.y);
                mma8(acc[0][ni], af[0], bf);
                mma8(acc[1][ni], af[1], bf);
            }
        }
        __syncthreads();
        if (++s == 3) s = 0;
    }

    // epilogue: logical cols (base+2t4, base+2t4+1); phys via perm if PERMC
    #pragma unroll
    for (int mi = 0; mi < 2; mi++) {
        const int row0 = bm + (wm << 5) + (mi << 4) + g;
        #pragma unroll
        for (int ni = 0; ni < 8; ni++) {
            const int base = bn + (wn << 6) + (ni << 3);
            const int lcol = base + (t4 << 1);
            const float b0 = bias[lcol], b1 = bias[lcol + 1];
            float v00 = acc[mi][ni][0] + b0, v01 = acc[mi][ni][1] + b1;
            float v10 = acc[mi][ni][2] + b0, v11 = acc[mi][ni][3] + b1;
            const size_t i0 = (size_t)row0 * N + lcol;
            const size_t i1 = i0 + (size_t)8 * N;
            if (HASRES) {
                v00 += res[i0]; v01 += res[i0 + 1];
                v10 += res[i1]; v11 += res[i1 + 1];
            }
            if (ACT == 1) {
                v00 = to_tf32(gelu_f(v00)); v01 = to_tf32(gelu_f(v01));
                v10 = to_tf32(gelu_f(v10)); v11 = to_tf32(gelu_f(v11));
            } else if (RND) {
                v00 = to_tf32(v00); v01 = to_tf32(v01);
                v10 = to_tf32(v10); v11 = to_tf32(v11);
            }
            if (PERMC) {
                const int p0 = (t4 < 2) ? (t4 << 2) : ((t4 << 2) - 7);
                const size_t r0i = (size_t)row0 * N + base;
                const size_t r1i = r0i + (size_t)8 * N;
                C[r0i + p0] = v00; C[r0i + p0 + 2] = v01;
                C[r1i + p0] = v10; C[r1i + p0 + 2] = v11;
            } else {
                *(float2*)&C[i0] = make_float2(v00, v01);
                *(float2*)&C[i1] = make_float2(v10, v11);
            }
        }
    }
}

// ---------------- causal flash attention (tf32 mma, online softmax) --------
// Q/K/V from fused qkv buffer (row stride 6144). O written k-permuted.
#define FSMEM 119552

__global__ __launch_bounds__(256) void flash_kernel(
    const float* __restrict__ QKV, float* __restrict__ O)
{
    extern __shared__ float smf[];
    float* Qs   = smf;                 // [64][132]
    float* Ks   = smf + 8448;          // [64][132]
    float* Vs   = smf + 16896;         // [64][132]
    float* Ss   = smf + 25344;         // [64][68]
    float* mrow = smf + 29696;
    float* lrow = smf + 29760;
    float* arow = smf + 29824;

    const int tid = threadIdx.x;
    const int warp = tid >> 5, lane = tid & 31;
    const int g = lane >> 2, t4 = lane & 3;
    const int wm = warp >> 1, wn = warp & 1;
    const int b = blockIdx.y >> 4, h = blockIdx.y & 15;
    const int q0 = blockIdx.x << 6;
    const size_t qbase = (size_t)b * 2048 * 6144 + (size_t)h * 128;
    const float* Qg = QKV + qbase;
    const float* Kg = QKV + qbase + 2048;
    const float* Vg = QKV + qbase + 4096;
    float*       Og = O + ((size_t)b * 2048) * 2048 + (size_t)h * 128;

    #pragma unroll
    for (int rr = 0; rr < 8; rr++) {
        const int f4 = tid + (rr << 8);
        const int row = f4 >> 5, c4 = f4 & 31;
        *(float4*)&Qs[row * 132 + (c4 << 2)] =
            *(const float4*)&Qg[(size_t)(q0 + row) * 6144 + (c4 << 2)];
    }
    if (tid < 64) { mrow[tid] = -1e30f; lrow[tid] = 0.f; }

    float o[2][4][4];
    #pragma unroll
    for (int mi = 0; mi < 2; mi++)
        #pragma unroll
        for (int ni = 0; ni < 4; ni++)
            #pragma unroll
            for (int c = 0; c < 4; c++) o[mi][ni][c] = 0.f;

    const int ntile = (q0 >> 6) + 1;
    for (int kt = 0; kt < ntile; kt++) {
        const int k0 = kt << 6;
        __syncthreads();
        #pragma unroll
        for (int rr = 0; rr < 8; rr++) {
            const int f4 = tid + (rr << 8);
            const int row = f4 >> 5, c4 = f4 & 31;
            *(float4*)&Ks[row * 132 + (c4 << 2)] =
                *(const float4*)&Kg[(size_t)(k0 + row) * 6144 + (c4 << 2)];
            *(float4*)&Vs[row * 132 + (c4 << 2)] =
                *(const float4*)&Vg[(size_t)(k0 + row) * 6144 + (c4 << 2)];
        }
        __syncthreads();

        // S = Q K^T (warp tile 16x32)
        {
            float sacc[4][4];
            #pragma unroll
            for (int ni = 0; ni < 4; ni++)
                #pragma unroll
                for (int c = 0; c < 4; c++) sacc[ni][c] = 0.f;
            const int m0 = wm << 4;
            #pragma unroll
            for (int kk = 0; kk < 16; kk++) {
                const int kb = kk << 3;
                uint32_t af[4];
                af[0] = __float_as_uint(Qs[(m0 + g    ) * 132 + kb + t4    ]);
                af[1] = __float_as_uint(Qs[(m0 + g + 8) * 132 + kb + t4    ]);
                af[2] = __float_as_uint(Qs[(m0 + g    ) * 132 + kb + t4 + 4]);
                af[3] = __float_as_uint(Qs[(m0 + g + 8) * 132 + kb + t4 + 4]);
                #pragma unroll
                for (int ni = 0; ni < 4; ni++) {
                    const int n = (wn << 5) + (ni << 3) + g;
                    uint32_t bf[2];
                    bf[0] = __float_as_uint(Ks[n * 132 + kb + t4    ]);
                    bf[1] = __float_as_uint(Ks[n * 132 + kb + t4 + 4]);
                    mma8(sacc[ni], af, bf);
                }
            }
            #pragma unroll
            for (int ni = 0; ni < 4; ni++) {
                const int col = (wn << 5) + (ni << 3) + (t4 << 1);
                const int r0 = m0 + g, r1 = m0 + g + 8;
                float v00 = sacc[ni][0] * 0.08838834764831845f;
                float v01 = sacc[ni][1] * 0.08838834764831845f;
                float v10 = sacc[ni][2] * 0.08838834764831845f;
                float v11 = sacc[ni][3] * 0.08838834764831845f;
                if (k0 + col     > q0 + r0) v00 = -1e30f;
                if (k0 + col + 1 > q0 + r0) v01 = -1e30f;
                if (k0 + col     > q0 + r1) v10 = -1e30f;
                if (k0 + col + 1 > q0 + r1) v11 = -1e30f;
                Ss[r0 * 68 + col] = v00; Ss[r0 * 68 + col + 1] = v01;
                Ss[r1 * 68 + col] = v10; Ss[r1 * 68 + col + 1] = v11;
            }
        }
        __syncthreads();

        // online softmax; P tf32-rounded
        {
            const int rid = tid >> 2, c0 = tid & 3;
            float mx = -1e30f;
            #pragma unroll
            for (int jc = c0; jc < 64; jc += 4) mx = fmaxf(mx, Ss[rid * 68 + jc]);
            mx = fmaxf(mx, __shfl_xor_sync(0xffffffffu, mx, 1));
            mx = fmaxf(mx, __shfl_xor_sync(0xffffffffu, mx, 2));
            const float mold = mrow[rid];
            const float mnew = fmaxf(mold, mx);
            float sum = 0.f;
            #pragma unroll
            for (int jc = c0; jc < 64; jc += 4) {
                const float p = to_tf32(__expf(Ss[rid * 68 + jc] - mnew));
                Ss[rid * 68 + jc] = p;
                sum += p;
            }
            sum += __shfl_xor_sync(0xffffffffu, sum, 1);
            sum += __shfl_xor_sync(0xffffffffu, sum, 2);
            if (c0 == 0) {
                arow[rid] = __expf(mold - mnew);
                lrow[rid] = lrow[rid] * arow[rid] + sum;
                mrow[rid] = mnew;
            }
        }
        __syncthreads();

        // O^T += V^T @ P^T (warp tile 32d x 32q)
        {
            const int d0 = wm << 5, qw = wn << 5;
            #pragma unroll
            for (int ni = 0; ni < 4; ni++) {
                const int cq = qw + (ni << 3) + (t4 << 1);
                const float a0 = arow[cq], a1 = arow[cq + 1];
                #pragma unroll
                for (int mi = 0; mi < 2; mi++) {
                    o[mi][ni][0] *= a0; o[mi][ni][1] *= a1;
                    o[mi][ni][2] *= a0; o[mi][ni][3] *= a1;
                }
            }
            #pragma unroll
            for (int k_ = 0; k_ < 8; k_++) {
                const int kb = k_ << 3;
                uint32_t af[2][4];
                #pragma unroll
                for (int mi = 0; mi < 2; mi++) {
                    const int dm = d0 + (mi << 4);
                    af[mi][0] = __float_as_uint(Vs[(kb + t4    ) * 132 + dm + g    ]);
                    af[mi][1] = __float_as_uint(Vs[(kb + t4    ) * 132 + dm + g + 8]);
                    af[mi][2] = __float_as_uint(Vs[(kb + t4 + 4) * 132 + dm + g    ]);
                    af[mi][3] = __float_as_uint(Vs[(kb + t4 + 4) * 132 + dm + g + 8]);
                }
                #pragma unroll
                for (int ni = 0; ni < 4; ni++) {
                    const int nq = qw + (ni << 3) + g;
                    uint32_t bf[2];
                    bf[0] = __float_as_uint(Ss[nq * 68 + kb + t4    ]);
                    bf[1] = __float_as_uint(Ss[nq * 68 + kb + t4 + 4]);
                    mma8(o[0][ni], af[0], bf);
                    mma8(o[1][ni], af[1], bf);
                }
            }
        }
    }

    // normalize + store O[q][d], d-index k-permuted for next GEMM's A
    __syncthreads();
    {
        const int d0 = wm << 5, qw = wn << 5;
        const int pg = (g < 4) ? (g << 1) : ((g << 1) - 7);
        #pragma unroll
        for (int ni = 0; ni < 4; ni++) {
            const int cq = qw + (ni << 3) + (t4 << 1);
            const float inv0 = 1.0f / lrow[cq], inv1 = 1.0f / lrow[cq + 1];
            #pragma unroll
            for (int mi = 0; mi < 2; mi++) {
                const int db = d0 + (mi << 4);
                Og[(size_t)(q0 + cq    ) * 2048 + db + pg    ] = to_tf32(o[mi][ni][0] * inv0);
                Og[(size_t)(q0 + cq + 1) * 2048 + db + pg    ] = to_tf32(o[mi][ni][1] * inv1);
                Og[(size_t)(q0 + cq    ) * 2048 + db + 8 + pg] = to_tf32(o[mi][ni][2] * inv0);
                Og[(size_t)(q0 + cq + 1) * 2048 + db + 8 + pg] = to_tf32(o[mi][ni][3] * inv1);
            }
        }
    }
}

// ---------------- host orchestration ---------------------------------------
extern "C" void kernel_launch(void* const* d_in, const int* in_sizes, int n_in,
                              void* d_out, int out_size)
{
    const float* x     = (const float*)d_in[0];
    const float* ln1_g = (const float*)d_in[2];
    const float* ln1_b = (const float*)d_in[3];
    const float* wq    = (const float*)d_in[4];
    const float* bq    = (const float*)d_in[5];
    const float* wk    = (const float*)d_in[6];
    const float* bk    = (const float*)d_in[7];
    const float* wv    = (const float*)d_in[8];
    const float* bv    = (const float*)d_in[9];
    const float* wo    = (const float*)d_in[10];
    const float* bo    = (const float*)d_in[11];
    const float* ln2_g = (const float*)d_in[12];
    const float* ln2_b = (const float*)d_in[13];
    const float* w_in  = (const float*)d_in[14];
    const float* b_in  = (const float*)d_in[15];
    const float* w_out = (const float*)d_in[16];
    const float* b_out = (const float*)d_in[17];
    float* out = (float*)d_out;

    float *xn, *qkv, *attn, *x1, *h, *wqkvt, *wot, *wint, *woutt, *bqkv;
    cudaGetSymbolAddress((void**)&xn,     g_xn);
    cudaGetSymbolAddress((void**)&qkv,    g_qkv);
    cudaGetSymbolAddress((void**)&attn,   g_attn);
    cudaGetSymbolAddress((void**)&x1,     g_x1);
    cudaGetSymbolAddress((void**)&h,      g_h);
    cudaGetSymbolAddress((void**)&wqkvt,  g_wqkvt);
    cudaGetSymbolAddress((void**)&wot,    g_wot);
    cudaGetSymbolAddress((void**)&wint,   g_wint);
    cudaGetSymbolAddress((void**)&woutt,  g_woutt);
    cudaGetSymbolAddress((void**)&bqkv,   g_bqkv);

    cudaFuncSetAttribute(flash_kernel,
                         cudaFuncAttributeMaxDynamicSharedMemorySize, FSMEM);
    cudaFuncSetAttribute(gemm_cp<0,0,1,0>,
                         cudaFuncAttributeMaxDynamicSharedMemorySize, GSMEM);
    cudaFuncSetAttribute(gemm_cp<0,1,0,0>,
                         cudaFuncAttributeMaxDynamicSharedMemorySize, GSMEM);
    cudaFuncSetAttribute(gemm_cp<1,0,0,1>,
                         cudaFuncAttributeMaxDynamicSharedMemorySize, GSMEM);

    // launch order arranged so ncu (-s 5 -c 1) captures the O-proj GEMM
    prep_a<<<12312, 256>>>(wq, wk, wv, bq, bk, bv);                     // 1
    prep_b<<<36864, 256>>>(wo, w_in, w_out);                            // 2
    ln_kernel<<<4096, 256>>>(x, ln1_g, ln1_b, xn);                      // 3
    gemm_cp<0,0,1,0><<<dim3(48, 32), 256, GSMEM>>>(                     // 4: QKV
        xn, wqkvt, bqkv, nullptr, qkv, 4096, 6144, 2048);
    flash_kernel<<<dim3(32, 32), 256, FSMEM>>>(qkv, attn);              // 5
    gemm_cp<0,1,0,0><<<dim3(16, 32), 256, GSMEM>>>(                     // 6: O-proj
        attn, wot, bo, x, x1, 4096, 2048, 2048);
    ln_kernel<<<4096, 256>>>(x1, ln2_g, ln2_b, xn);                     // 7
    gemm_cp<1,0,0,1><<<dim3(64, 32), 256, GSMEM>>>(                     // 8: MLP in
        xn, wint, b_in, nullptr, h, 4096, 8192, 2048);
    gemm_cp<0,1,0,0><<<dim3(16, 32), 256, GSMEM>>>(                     // 9: MLP out
        h, woutt, b_out, x1, out, 4096, 2048, 8192);
}

// round 8
// speedup vs baseline: 1.7792x; 1.0358x over previous
#include <cuda_runtime.h>
#include <cstdint>
#include <math.h>

// Problem dims: B=2, S=2048, D=2048, H=16, DH=128, DFF=8192
#define BSD 8388608   // B*S*D
#define BSF 33554432  // B*S*DFF

// ---------------- scratch (static device globals; no runtime allocation) ---
__device__ float g_xn[BSD];         // LN out (k-permuted along D)
__device__ float g_qkv[25165824];   // [4096][6144] q|k|v
__device__ float g_attn[BSD];       // flash out (k-permuted along D)
__device__ float g_x1[BSD];
__device__ float g_h[BSF];          // gelu out (k-permuted along DFF)
// transposed [N,K] + tf32-rounded + k-permuted weights
__device__ float g_wqkvt[12582912]; // [6144][2048]
__device__ float g_wot[4194304];    // [2048][2048]
__device__ float g_wint[16777216];  // [8192][2048]
__device__ float g_woutt[16777216]; // [2048][8192]
__device__ float g_bqkv[6144];

// ---------------- helpers --------------------------------------------------
__device__ __forceinline__ float to_tf32(float x) {
    float r; asm("cvt.rna.tf32.f32 %0, %1;" : "=f"(r) : "f"(x)); return r;
}
__device__ __forceinline__ uint32_t smem_u32(const void* p) {
    uint32_t a;
    asm("{ .reg .u64 t; cvta.to.shared.u64 t, %1; cvt.u32.u64 %0, t; }"
        : "=r"(a) : "l"(p));
    return a;
}
__device__ __forceinline__ void cp16(uint32_t s, const void* g) {
    asm volatile("cp.async.cg.shared.global [%0], [%1], 16;" :: "r"(s), "l"(g));
}
__device__ __forceinline__ void mma8(float* d, const uint32_t* a, const uint32_t* b) {
    asm volatile(
        "mma.sync.aligned.m16n8k8.row.col.f32.tf32.tf32.f32 "
        "{%0,%1,%2,%3}, {%4,%5,%6,%7}, {%8,%9}, {%0,%1,%2,%3};\n"
        : "+f"(d[0]), "+f"(d[1]), "+f"(d[2]), "+f"(d[3])
        : "r"(a[0]), "r"(a[1]), "r"(a[2]), "r"(a[3]), "r"(b[0]), "r"(b[1]));
}
__device__ __forceinline__ float gelu_f(float v) {
    return 0.5f * v * (1.0f + erff(v * 0.70710678118654752f));
}
// k-permutation within 8-groups: logical l -> phys (l<4 ? 2l : 2(l-4)+1)
__device__ __forceinline__ int permc(int x) {
    const int l = x & 7;
    return (x & 24) | ((l < 4) ? (l << 1) : (((l - 4) << 1) | 1));
}

// ---------------- weight prep: transpose [K,N]->[N,K], round, k-permute ----
__device__ void tp_tile(const float* __restrict__ src, float* __restrict__ dst,
                        int K, int N, int t)
{
    __shared__ float tbuf[32][33];
    const int tn = N >> 5;
    const int n0 = (t % tn) << 5, k0 = (t / tn) << 5;
    const int x = threadIdx.x & 31, y = threadIdx.x >> 5;
    #pragma unroll
    for (int i = 0; i < 32; i += 8)
        tbuf[y + i][x] = src[(size_t)(k0 + y + i) * N + n0 + x];
    __syncthreads();
    const int kp = k0 + permc(x);
    #pragma unroll
    for (int i = 0; i < 32; i += 8)
        dst[(size_t)(n0 + y + i) * K + kp] = to_tf32(tbuf[x][y + i]);
}

__global__ __launch_bounds__(256) void prep_a(
    const float* __restrict__ wq, const float* __restrict__ wk,
    const float* __restrict__ wv, const float* __restrict__ bq,
    const float* __restrict__ bk, const float* __restrict__ bv)
{
    const int blk = blockIdx.x;
    if (blk < 12288) {
        const int w = blk >> 12, t = blk & 4095;
        const float* src = (w == 0) ? wq : (w == 1) ? wk : wv;
        tp_tile(src, g_wqkvt + (size_t)w * 4194304, 2048, 2048, t);
    } else {
        const int idx = ((blk - 12288) << 8) + threadIdx.x;
        if (idx < 6144) {
            const int sel = idx >> 11;
            const float* b = (sel == 0) ? bq : (sel == 1) ? bk : bv;
            g_bqkv[idx] = b[idx & 2047];
        }
    }
}

__global__ __launch_bounds__(256) void prep_b(
    const float* __restrict__ wo, const float* __restrict__ w_in,
    const float* __restrict__ w_out)
{
    const int blk = blockIdx.x;
    if (blk < 4096)        tp_tile(wo,    g_wot,   2048, 2048, blk);
    else if (blk < 20480)  tp_tile(w_in,  g_wint,  2048, 8192, blk - 4096);
    else                   tp_tile(w_out, g_woutt, 8192, 2048, blk - 20480);
}

// ---------------- block reduce ---------------------------------------------
__device__ __forceinline__ float block_sum256(float v) {
    __shared__ float red[8];
    #pragma unroll
    for (int o = 16; o; o >>= 1) v += __shfl_xor_sync(0xffffffffu, v, o);
    const int w = threadIdx.x >> 5, l = threadIdx.x & 31;
    __syncthreads();
    if (l == 0) red[w] = v;
    __syncthreads();
    float t = red[l & 7];
    t += __shfl_xor_sync(0xffffffffu, t, 1);
    t += __shfl_xor_sync(0xffffffffu, t, 2);
    t += __shfl_xor_sync(0xffffffffu, t, 4);
    return t;
}

// ---------------- LayerNorm (tf32-rounded, k-permuted output) --------------
__global__ __launch_bounds__(256) void ln_kernel(
    const float* __restrict__ x, const float* __restrict__ gw,
    const float* __restrict__ bw, float* __restrict__ y)
{
    const size_t base = (size_t)blockIdx.x * 2048;
    const int c0 = threadIdx.x << 3;
    const float4 v0 = *(const float4*)&x[base + c0];
    const float4 v1 = *(const float4*)&x[base + c0 + 4];

    float s = v0.x + v0.y + v0.z + v0.w + v1.x + v1.y + v1.z + v1.w;
    const float mean = block_sum256(s) * (1.0f / 2048.0f);

    float d[8];
    d[0] = v0.x - mean; d[1] = v0.y - mean; d[2] = v0.z - mean; d[3] = v0.w - mean;
    d[4] = v1.x - mean; d[5] = v1.y - mean; d[6] = v1.z - mean; d[7] = v1.w - mean;
    float q = 0.f;
    #pragma unroll
    for (int i = 0; i < 8; i++) q += d[i] * d[i];
    const float var = block_sum256(q) * (1.0f / 2048.0f);
    const float rs = rsqrtf(var + 1e-5f);

    const float4 g0 = *(const float4*)&gw[c0];
    const float4 g1 = *(const float4*)&gw[c0 + 4];
    const float4 b0 = *(const float4*)&bw[c0];
    const float4 b1 = *(const float4*)&bw[c0 + 4];
    const float ga[8] = {g0.x, g0.y, g0.z, g0.w, g1.x, g1.y, g1.z, g1.w};
    const float ba[8] = {b0.x, b0.y, b0.z, b0.w, b1.x, b1.y, b1.z, b1.w};

    float o[8];
    #pragma unroll
    for (int i = 0; i < 8; i++) o[i] = to_tf32(d[i] * rs * ga[i] + ba[i]);

    #pragma unroll
    for (int i = 0; i < 4; i++)
        *(float2*)&y[base + c0 + (i << 1)] = make_float2(o[i], o[i + 4]);
}

// ---------------- TF32 GEMM: pointer-inc copies, 1 barrier/k-tile ----------
// C[M,N] = A[M,K] @ Wt[N,K]^T (+bias)(+res)(+gelu)(rnd). A,Wt k-permuted.
// CTA 128x128, K-tile 32, 8 warps 4(m)x2(n). 3 stages x 32KB = 96KB smem.
#define GSMEM 98304

template<int ACT, int HASRES, int RND, int PERMC>
__global__ __launch_bounds__(256, 2) void gemm_cp(
    const float* __restrict__ A, const float* __restrict__ Wt,
    const float* __restrict__ bias, const float* __restrict__ res,
    float* __restrict__ C, int M, int N, int K)
{
    extern __shared__ float sm[];
    const uint32_t sb = smem_u32(sm);
    const int tid = threadIdx.x;
    const int warp = tid >> 5, lane = tid & 31;
    const int wm = warp >> 1, wn = warp & 1;
    const int g = lane >> 2, t4 = lane & 3;
    const int bm = blockIdx.y << 7, bn = blockIdx.x << 7;

    const float* Ab = A  + (size_t)bm * K;
    const float* Bb = Wt + (size_t)bn * K;
    const int KT = K >> 5;

    // copy geometry: running global pointers + fixed swizzled smem offsets
    const int r0 = tid >> 3;
    const int cc = (tid & 7) << 2;
    const uint32_t dcol = (uint32_t)((cc ^ ((r0 & 3) << 3)) << 2);  // bytes
    const float* ga[4]; const float* gb[4];
    uint32_t da[4], db[4];
    #pragma unroll
    for (int i = 0; i < 4; i++) {
        const int row = r0 + (i << 5);
        ga[i] = Ab + (size_t)row * K + cc;
        gb[i] = Bb + (size_t)row * K + cc;
        da[i] = (uint32_t)(row * 128) + dcol;
        db[i] = 16384u + (uint32_t)(row * 128) + dcol;
    }

    float acc[2][8][4];
    #pragma unroll
    for (int a = 0; a < 2; a++)
        #pragma unroll
        for (int b2 = 0; b2 < 8; b2++)
            #pragma unroll
            for (int c = 0; c < 4; c++) acc[a][b2][c] = 0.f;

    auto issue = [&](int s) {
        const uint32_t st = sb + (uint32_t)s * 32768u;
        #pragma unroll
        for (int i = 0; i < 4; i++) { cp16(st + da[i], ga[i]); ga[i] += 32; }
        #pragma unroll
        for (int i = 0; i < 4; i++) { cp16(st + db[i], gb[i]); gb[i] += 32; }
        asm volatile("cp.async.commit_group;" ::: "memory");
    };

    issue(0);
    issue(1);

    // fragment k-offsets: ((ks<<3) ^ swz) | (t4<<1)  (disjoint bit-fields)
    const int swz = (g & 3) << 3;
    int kcs[4];
    #pragma unroll
    for (int ks = 0; ks < 4; ks++) kcs[ks] = ((ks << 3) ^ swz) | (t4 << 1);

    int s = 0;
    for (int kt = 0; kt < KT; kt++) {
        if (kt + 1 < KT) asm volatile("cp.async.wait_group 1;" ::: "memory");
        else             asm volatile("cp.async.wait_group 0;" ::: "memory");
        __syncthreads();   // single barrier: orders copies + prev-iter reads
        if (kt + 2 < KT) {
            int ns = s + 2; if (ns >= 3) ns -= 3;
            issue(ns);
        }
        const float* As = sm + s * 8192;
        const float* Bs = As + 4096;

        #pragma unroll
        for (int ks = 0; ks < 4; ks++) {
            const int kc = kcs[ks];
            uint32_t af[2][4];
            #pragma unroll
            for (int mi = 0; mi < 2; mi++) {
                const int mr = (wm << 5) + (mi << 4) + g;
                const float2 a02 = *(const float2*)&As[mr * 32 + kc];
                const float2 a13 = *(const float2*)&As[(mr + 8) * 32 + kc];
                af[mi][0] = __float_as_uint(a02.x);
                af[mi][1] = __float_as_uint(a13.x);
                af[mi][2] = __float_as_uint(a02.y);
                af[mi][3] = __float_as_uint(a13.y);
            }
            #pragma unroll
            for (int ni = 0; ni < 8; ni++) {
                const int nc = (wn << 6) + (ni << 3) + g;
                const float2 b01 = *(const float2*)&Bs[nc * 32 + kc];
                uint32_t bf[2];
                bf[0] = __float_as_uint(b01.x);
                bf[1] = __float_as_uint(b01.y);
                mma8(acc[0][ni], af[0], bf);
                mma8(acc[1][ni], af[1], bf);
            }
        }
        if (++s == 3) s = 0;
    }

    // epilogue
    #pragma unroll
    for (int mi = 0; mi < 2; mi++) {
        const int row0 = bm + (wm << 5) + (mi << 4) + g;
        #pragma unroll
        for (int ni = 0; ni < 8; ni++) {
            const int base = bn + (wn << 6) + (ni << 3);
            const int lcol = base + (t4 << 1);
            const float b0 = bias[lcol], b1 = bias[lcol + 1];
            float v00 = acc[mi][ni][0] + b0, v01 = acc[mi][ni][1] + b1;
            float v10 = acc[mi][ni][2] + b0, v11 = acc[mi][ni][3] + b1;
            const size_t i0 = (size_t)row0 * N + lcol;
            const size_t i1 = i0 + (size_t)8 * N;
            if (HASRES) {
                v00 += res[i0]; v01 += res[i0 + 1];
                v10 += res[i1]; v11 += res[i1 + 1];
            }
            if (ACT == 1) {
                v00 = to_tf32(gelu_f(v00)); v01 = to_tf32(gelu_f(v01));
                v10 = to_tf32(gelu_f(v10)); v11 = to_tf32(gelu_f(v11));
            } else if (RND) {
                v00 = to_tf32(v00); v01 = to_tf32(v01);
                v10 = to_tf32(v10); v11 = to_tf32(v11);
            }
            if (PERMC) {
                const int p0 = (t4 < 2) ? (t4 << 2) : ((t4 << 2) - 7);
                const size_t r0i = (size_t)row0 * N + base;
                const size_t r1i = r0i + (size_t)8 * N;
                C[r0i + p0] = v00; C[r0i + p0 + 2] = v01;
                C[r1i + p0] = v10; C[r1i + p0 + 2] = v11;
            } else {
                *(float2*)&C[i0] = make_float2(v00, v01);
                *(float2*)&C[i1] = make_float2(v10, v11);
            }
        }
    }
}

// ---------------- causal flash attention (tf32 mma, online softmax) --------
#define FSMEM 119552

__global__ __launch_bounds__(256) void flash_kernel(
    const float* __restrict__ QKV, float* __restrict__ O)
{
    extern __shared__ float smf[];
    float* Qs   = smf;                 // [64][132]
    float* Ks   = smf + 8448;          // [64][132]
    float* Vs   = smf + 16896;         // [64][132]
    float* Ss   = smf + 25344;         // [64][68]
    float* mrow = smf + 29696;
    float* lrow = smf + 29760;
    float* arow = smf + 29824;

    const int tid = threadIdx.x;
    const int warp = tid >> 5, lane = tid & 31;
    const int g = lane >> 2, t4 = lane & 3;
    const int wm = warp >> 1, wn = warp & 1;
    const int b = blockIdx.y >> 4, h = blockIdx.y & 15;
    const int q0 = blockIdx.x << 6;
    const size_t qbase = (size_t)b * 2048 * 6144 + (size_t)h * 128;
    const float* Qg = QKV + qbase;
    const float* Kg = QKV + qbase + 2048;
    const float* Vg = QKV + qbase + 4096;
    float*       Og = O + ((size_t)b * 2048) * 2048 + (size_t)h * 128;

    #pragma unroll
    for (int rr = 0; rr < 8; rr++) {
        const int f4 = tid + (rr << 8);
        const int row = f4 >> 5, c4 = f4 & 31;
        *(float4*)&Qs[row * 132 + (c4 << 2)] =
            *(const float4*)&Qg[(size_t)(q0 + row) * 6144 + (c4 << 2)];
    }
    if (tid < 64) { mrow[tid] = -1e30f; lrow[tid] = 0.f; }

    float o[2][4][4];
    #pragma unroll
    for (int mi = 0; mi < 2; mi++)
        #pragma unroll
        for (int ni = 0; ni < 4; ni++)
            #pragma unroll
            for (int c = 0; c < 4; c++) o[mi][ni][c] = 0.f;

    const int ntile = (q0 >> 6) + 1;
    for (int kt = 0; kt < ntile; kt++) {
        const int k0 = kt << 6;
        __syncthreads();
        #pragma unroll
        for (int rr = 0; rr < 8; rr++) {
            const int f4 = tid + (rr << 8);
            const int row = f4 >> 5, c4 = f4 & 31;
            *(float4*)&Ks[row * 132 + (c4 << 2)] =
                *(const float4*)&Kg[(size_t)(k0 + row) * 6144 + (c4 << 2)];
            *(float4*)&Vs[row * 132 + (c4 << 2)] =
                *(const float4*)&Vg[(size_t)(k0 + row) * 6144 + (c4 << 2)];
        }
        __syncthreads();

        // S = Q K^T (warp tile 16x32)
        {
            float sacc[4][4];
            #pragma unroll
            for (int ni = 0; ni < 4; ni++)
                #pragma unroll
                for (int c = 0; c < 4; c++) sacc[ni][c] = 0.f;
            const int m0 = wm << 4;
            #pragma unroll
            for (int kk = 0; kk < 16; kk++) {
                const int kb = kk << 3;
                uint32_t af[4];
                af[0] = __float_as_uint(Qs[(m0 + g    ) * 132 + kb + t4    ]);
                af[1] = __float_as_uint(Qs[(m0 + g + 8) * 132 + kb + t4    ]);
                af[2] = __float_as_uint(Qs[(m0 + g    ) * 132 + kb + t4 + 4]);
                af[3] = __float_as_uint(Qs[(m0 + g + 8) * 132 + kb + t4 + 4]);
                #pragma unroll
                for (int ni = 0; ni < 4; ni++) {
                    const int n = (wn << 5) + (ni << 3) + g;
                    uint32_t bf[2];
                    bf[0] = __float_as_uint(Ks[n * 132 + kb + t4    ]);
                    bf[1] = __float_as_uint(Ks[n * 132 + kb + t4 + 4]);
                    mma8(sacc[ni], af, bf);
                }
            }
            #pragma unroll
            for (int ni = 0; ni < 4; ni++) {
                const int col = (wn << 5) + (ni << 3) + (t4 << 1);
                const int r0 = m0 + g, r1 = m0 + g + 8;
                float v00 = sacc[ni][0] * 0.08838834764831845f;
                float v01 = sacc[ni][1] * 0.08838834764831845f;
                float v10 = sacc[ni][2] * 0.08838834764831845f;
                float v11 = sacc[ni][3] * 0.08838834764831845f;
                if (k0 + col     > q0 + r0) v00 = -1e30f;
                if (k0 + col + 1 > q0 + r0) v01 = -1e30f;
                if (k0 + col     > q0 + r1) v10 = -1e30f;
                if (k0 + col + 1 > q0 + r1) v11 = -1e30f;
                Ss[r0 * 68 + col] = v00; Ss[r0 * 68 + col + 1] = v01;
                Ss[r1 * 68 + col] = v10; Ss[r1 * 68 + col + 1] = v11;
            }
        }
        __syncthreads();

        // online softmax; P tf32-rounded
        {
            const int rid = tid >> 2, c0 = tid & 3;
            float mx = -1e30f;
            #pragma unroll
            for (int jc = c0; jc < 64; jc += 4) mx = fmaxf(mx, Ss[rid * 68 + jc]);
            mx = fmaxf(mx, __shfl_xor_sync(0xffffffffu, mx, 1));
            mx = fmaxf(mx, __shfl_xor_sync(0xffffffffu, mx, 2));
            const float mold = mrow[rid];
            const float mnew = fmaxf(mold, mx);
            float sum = 0.f;
            #pragma unroll
            for (int jc = c0; jc < 64; jc += 4) {
                const float p = to_tf32(__expf(Ss[rid * 68 + jc] - mnew));
                Ss[rid * 68 + jc] = p;
                sum += p;
            }
            sum += __shfl_xor_sync(0xffffffffu, sum, 1);
            sum += __shfl_xor_sync(0xffffffffu, sum, 2);
            if (c0 == 0) {
                arow[rid] = __expf(mold - mnew);
                lrow[rid] = lrow[rid] * arow[rid] + sum;
                mrow[rid] = mnew;
            }
        }
        __syncthreads();

        // O^T += V^T @ P^T (warp tile 32d x 32q)
        {
            const int d0 = wm << 5, qw = wn << 5;
            #pragma unroll
            for (int ni = 0; ni < 4; ni++) {
                const int cq = qw + (ni << 3) + (t4 << 1);
                const float a0 = arow[cq], a1 = arow[cq + 1];
                #pragma unroll
                for (int mi = 0; mi < 2; mi++) {
                    o[mi][ni][0] *= a0; o[mi][ni][1] *= a1;
                    o[mi][ni][2] *= a0; o[mi][ni][3] *= a1;
                }
            }
            #pragma unroll
            for (int k_ = 0; k_ < 8; k_++) {
                const int kb = k_ << 3;
                uint32_t af[2][4];
                #pragma unroll
                for (int mi = 0; mi < 2; mi++) {
                    const int dm = d0 + (mi << 4);
                    af[mi][0] = __float_as_uint(Vs[(kb + t4    ) * 132 + dm + g    ]);
                    af[mi][1] = __float_as_uint(Vs[(kb + t4    ) * 132 + dm + g + 8]);
                    af[mi][2] = __float_as_uint(Vs[(kb + t4 + 4) * 132 + dm + g    ]);
                    af[mi][3] = __float_as_uint(Vs[(kb + t4 + 4) * 132 + dm + g + 8]);
                }
                #pragma unroll
                for (int ni = 0; ni < 4; ni++) {
                    const int nq = qw + (ni << 3) + g;
                    uint32_t bf[2];
                    bf[0] = __float_as_uint(Ss[nq * 68 + kb + t4    ]);
                    bf[1] = __float_as_uint(Ss[nq * 68 + kb + t4 + 4]);
                    mma8(o[0][ni], af[0], bf);
                    mma8(o[1][ni], af[1], bf);
                }
            }
        }
    }

    // normalize + store O[q][d], d-index k-permuted for next GEMM's A
    __syncthreads();
    {
        const int d0 = wm << 5, qw = wn << 5;
        const int pg = (g < 4) ? (g << 1) : ((g << 1) - 7);
        #pragma unroll
        for (int ni = 0; ni < 4; ni++) {
            const int cq = qw + (ni << 3) + (t4 << 1);
            const float inv0 = 1.0f / lrow[cq], inv1 = 1.0f / lrow[cq + 1];
            #pragma unroll
            for (int mi = 0; mi < 2; mi++) {
                const int db = d0 + (mi << 4);
                Og[(size_t)(q0 + cq    ) * 2048 + db + pg    ] = to_tf32(o[mi][ni][0] * inv0);
                Og[(size_t)(q0 + cq + 1) * 2048 + db + pg    ] = to_tf32(o[mi][ni][1] * inv1);
                Og[(size_t)(q0 + cq    ) * 2048 + db + 8 + pg] = to_tf32(o[mi][ni][2] * inv0);
                Og[(size_t)(q0 + cq + 1) * 2048 + db + 8 + pg] = to_tf32(o[mi][ni][3] * inv1);
            }
        }
    }
}

// ---------------- host orchestration ---------------------------------------
extern "C" void kernel_launch(void* const* d_in, const int* in_sizes, int n_in,
                              void* d_out, int out_size)
{
    const float* x     = (const float*)d_in[0];
    const float* ln1_g = (const float*)d_in[2];
    const float* ln1_b = (const float*)d_in[3];
    const float* wq    = (const float*)d_in[4];
    const float* bq    = (const float*)d_in[5];
    const float* wk    = (const float*)d_in[6];
    const float* bk    = (const float*)d_in[7];
    const float* wv    = (const float*)d_in[8];
    const float* bv    = (const float*)d_in[9];
    const float* wo    = (const float*)d_in[10];
    const float* bo    = (const float*)d_in[11];
    const float* ln2_g = (const float*)d_in[12];
    const float* ln2_b = (const float*)d_in[13];
    const float* w_in  = (const float*)d_in[14];
    const float* b_in  = (const float*)d_in[15];
    const float* w_out = (const float*)d_in[16];
    const float* b_out = (const float*)d_in[17];
    float* out = (float*)d_out;

    float *xn, *qkv, *attn, *x1, *h, *wqkvt, *wot, *wint, *woutt, *bqkv;
    cudaGetSymbolAddress((void**)&xn,     g_xn);
    cudaGetSymbolAddress((void**)&qkv,    g_qkv);
    cudaGetSymbolAddress((void**)&attn,   g_attn);
    cudaGetSymbolAddress((void**)&x1,     g_x1);
    cudaGetSymbolAddress((void**)&h,      g_h);
    cudaGetSymbolAddress((void**)&wqkvt,  g_wqkvt);
    cudaGetSymbolAddress((void**)&wot,    g_wot);
    cudaGetSymbolAddress((void**)&wint,   g_wint);
    cudaGetSymbolAddress((void**)&woutt,  g_woutt);
    cudaGetSymbolAddress((void**)&bqkv,   g_bqkv);

    cudaFuncSetAttribute(flash_kernel,
                         cudaFuncAttributeMaxDynamicSharedMemorySize, FSMEM);
    cudaFuncSetAttribute(gemm_cp<0,0,1,0>,
                         cudaFuncAttributeMaxDynamicSharedMemorySize, GSMEM);
    cudaFuncSetAttribute(gemm_cp<0,1,0,0>,
                         cudaFuncAttributeMaxDynamicSharedMemorySize, GSMEM);
    cudaFuncSetAttribute(gemm_cp<1,0,0,1>,
                         cudaFuncAttributeMaxDynamicSharedMemorySize, GSMEM);

    // launch order: ncu (-s 5 -c 1) captures slot 6 area (GEMMs)
    prep_a<<<12312, 256>>>(wq, wk, wv, bq, bk, bv);                     // 1
    prep_b<<<36864, 256>>>(wo, w_in, w_out);                            // 2
    ln_kernel<<<4096, 256>>>(x, ln1_g, ln1_b, xn);                      // 3
    gemm_cp<0,0,1,0><<<dim3(48, 32), 256, GSMEM>>>(                     // 4: QKV
        xn, wqkvt, bqkv, nullptr, qkv, 4096, 6144, 2048);
    flash_kernel<<<dim3(32, 32), 256, FSMEM>>>(qkv, attn);              // 5
    gemm_cp<0,1,0,0><<<dim3(16, 32), 256, GSMEM>>>(                     // 6: O-proj
        attn, wot, bo, x, x1, 4096, 2048, 2048);
    ln_kernel<<<4096, 256>>>(x1, ln2_g, ln2_b, xn);                     // 7
    gemm_cp<1,0,0,1><<<dim3(64, 32), 256, GSMEM>>>(                     // 8: MLP in
        xn, wint, b_in, nullptr, h, 4096, 8192, 2048);
    gemm_cp<0,1,0,0><<<dim3(16, 32), 256, GSMEM>>>(                     // 9: MLP out
        h, woutt, b_out, x1, out, 4096, 2048, 8192);
}